// round 12
// baseline (speedup 1.0000x reference)
#include <cuda_runtime.h>
#include <cuda_bf16.h>

#define N_NODES 50000
#define N_EDGES 200000
#define MUL 16
#define ALPHA 0.17677669529663687f
#define INV_SQRT3 0.5773502691896258f
#define AIS (ALPHA * INV_SQRT3)
#define BN_EPS 1e-5f

typedef unsigned long long ull;
typedef unsigned int u32;

// ---------------- mma / ldmatrix / cp.async (baseline PTX, no 'a' gates) ----------------
__device__ __forceinline__ u32 smem_u32(const void* p) {
    u32 a;
    asm("{ .reg .u64 t; cvta.to.shared.u64 t, %1; cvt.u32.u64 %0, t; }" : "=r"(a) : "l"(p));
    return a;
}
__device__ __forceinline__ void ldsm4(u32& r0, u32& r1, u32& r2, u32& r3, u32 addr) {
    asm volatile("ldmatrix.sync.aligned.m8n8.x4.shared.b16 {%0,%1,%2,%3}, [%4];"
                 : "=r"(r0), "=r"(r1), "=r"(r2), "=r"(r3) : "r"(addr));
}
__device__ __forceinline__ void mma16816(float* d, const u32* a, u32 b0, u32 b1) {
    asm volatile(
        "mma.sync.aligned.m16n8k16.row.col.f32.bf16.bf16.f32 "
        "{%0,%1,%2,%3}, {%4,%5,%6,%7}, {%8,%9}, {%0,%1,%2,%3};"
        : "+f"(d[0]), "+f"(d[1]), "+f"(d[2]), "+f"(d[3])
        : "r"(a[0]), "r"(a[1]), "r"(a[2]), "r"(a[3]), "r"(b0), "r"(b1));
}
__device__ __forceinline__ void cpasync16(u32 dst, const void* src) {
    asm volatile("cp.async.ca.shared.global [%0], [%1], 16;" :: "r"(dst), "l"(src) : "memory");
}
#define CP_COMMIT() asm volatile("cp.async.commit_group;" ::: "memory")
#define CP_WAIT0() asm volatile("cp.async.wait_group 0;" ::: "memory")
#define CP_WAIT1() asm volatile("cp.async.wait_group 1;" ::: "memory")
#define CP_WAIT2() asm volatile("cp.async.wait_group 2;" ::: "memory")
#define SWX(rr, qq) ((((qq) ^ ((rr) & 7)) << 4) + (rr) * 128)

// pack two fp32 -> bf16x2 hi/lo split
__device__ __forceinline__ void split_pack(float va, float vb, u32& hi, u32& lo) {
    __nv_bfloat16 ha = __float2bfloat16(va), hb = __float2bfloat16(vb);
    float la = va - __bfloat162float(ha), lb = vb - __bfloat162float(hb);
    __nv_bfloat162 hp, lp;
    hp.x = ha; hp.y = hb;
    lp.x = __float2bfloat16(la); lp.y = __float2bfloat16(lb);
    hi = *(u32*)&hp;
    lo = *(u32*)&lp;
}

// ---------------- scratch ----------------
__device__ __align__(16) __nv_bfloat16 g_BThi[1024 * 64];
__device__ __align__(16) __nv_bfloat16 g_BTlo[1024 * 64];
__device__ __align__(16) __nv_bfloat16 g_W1Thi[64 * 64];
__device__ __align__(16) __nv_bfloat16 g_W1Tlo[64 * 64];
__device__ float g_agg[N_NODES * 64];   // zero on first run (BSS); restored by k_stats
__device__ float g_cnt[N_NODES];        // same invariant
__device__ float g_out[N_NODES * 64];
__device__ float g_stats[48];
__device__ float g_norm[48];

// ---------------- kernel 0: prep (zero g_stats + split w2^T and w1^T) ----------------
__global__ void k_prep(const float* __restrict__ w2, const float* __restrict__ w1) {
    int idx = blockIdx.x * blockDim.x + threadIdx.x;
    int stride = gridDim.x * blockDim.x;
    if (idx < 48) g_stats[idx] = 0.0f;

    // w2 split: g_BT[c][j] = split(w2[j][c])
    for (int i = idx; i < 65536; i += stride) {
        int j = i >> 10, c = i & 1023;
        float v = w2[i];
        __nv_bfloat16 hi = __float2bfloat16(v);
        g_BThi[c * 64 + j] = hi;
        g_BTlo[c * 64 + j] = __float2bfloat16(v - __bfloat162float(hi));
    }
    // w1 split: g_W1T[c][f] = split(w1[f][c])
    if (idx < 4096) {
        int f = idx >> 6, c = idx & 63;
        float v = w1[idx];
        __nv_bfloat16 hi = __float2bfloat16(v);
        g_W1Thi[c * 64 + f] = hi;
        g_W1Tlo[c * 64 + f] = __float2bfloat16(v - __bfloat162float(hi));
    }
}

// ---------------- kernel 1: fused GEMM1 + GEMM2 + TP + scatter ----------------
// 256 threads, 128 edges/block, 2 blocks/SM, warp owns 16 edges.
// B ring: 4 x 16KB compact XOR-swizzled buffers; copies lead compute by 3 slices.
// w1T occupies ring buf 0 during the GEMM1 prologue; B slices 0-2 fill bufs 1-3.
// Slice sl computes from buf (sl+1)&3; iter sl issues slice sl+3 into buf (sl+4)&3.
#define OFF_B 0           // 4 x 16384 ring
#define OFF_CX 65536      // [16][128] AIS*xs
#define OFF_CB 73728      // [16][128] AIS*(xv.sv)
#define OFF_CD 81920      // [48][128] AIS*ss*xv
#define OFF_B2 106496     // [1024] bias2
#define OFF_SHS 110592    // [128][4]; slot 0 -> fac = ss/INV_SQRT3 after coeff build
#define SMEM_TP 112640

__global__ __launch_bounds__(256, 2) void k_tp(const float* __restrict__ node_attr,
                                               const float* __restrict__ edge_sh,
                                               const float* __restrict__ b2,
                                               const int* __restrict__ edge_index,
                                               const float* __restrict__ ea,
                                               const float* __restrict__ b1g) {
    extern __shared__ __align__(16) char smem[];
    float* cX = (float*)(smem + OFF_CX);
    float* cB = (float*)(smem + OFF_CB);
    float* cD = (float*)(smem + OFF_CD);
    float* b2s = (float*)(smem + OFF_B2);
    float* shs = (float*)(smem + OFF_SHS);
    __shared__ int srcs[128], dsts[128];

    int tid = threadIdx.x;
    int lane = tid & 31;
    int wid = tid >> 5;
    int e0 = blockIdx.x * 128;
    u32 sbase = smem_u32(smem);

    if (tid < 128) {
        int e = e0 + tid;
        bool val = e < N_EDGES;
        float4 sh = val ? ((const float4*)edge_sh)[e] : make_float4(0, 0, 0, 0);
        *(float4*)&shs[tid * 4] = sh;
        srcs[tid] = val ? edge_index[e] : 0;
        dsts[tid] = val ? edge_index[N_EDGES + e] : -1;
    }
    for (int idx = tid; idx < 1024; idx += 256) b2s[idx] = b2[idx];
    __syncthreads();

    // stage w1T hi/lo into ring buf 0 (compact swizzled)
#pragma unroll 1
    for (int idx = tid; idx < 1024; idx += 256) {
        int half = idx >> 9, rem = idx & 511;
        int rr = rem >> 3, qq = rem & 7;
        const char* srcb = (const char*)(half ? g_W1Tlo : g_W1Thi);
        cpasync16(sbase + OFF_B + half * 8192 + SWX(rr, qq), srcb + rr * 128 + qq * 16);
    }
    CP_COMMIT();

    // coefficients [i][128e] (overlaps w1T copy)
    for (int idx = tid; idx < 2048; idx += 256) {
        int e = idx >> 4, i = idx & 15;
        int d = dsts[e];
        float ss = shs[e * 4], s1 = shs[e * 4 + 1], s2 = shs[e * 4 + 2], s3 = shs[e * 4 + 3];
        float xs = 0, x0 = 0, x1 = 0, x2 = 0;
        if (d >= 0) {
            xs = node_attr[d * 64 + i];
            const float* xp = &node_attr[d * 64 + 16 + 3 * i];
            x0 = xp[0]; x1 = xp[1]; x2 = xp[2];
        }
        cX[i * 128 + e] = AIS * xs;
        cB[i * 128 + e] = AIS * (x0 * s1 + x1 * s2 + x2 * s3);
        cD[(0 * 16 + i) * 128 + e] = AIS * ss * x0;
        cD[(1 * 16 + i) * 128 + e] = AIS * ss * x1;
        cD[(2 * 16 + i) * 128 + e] = AIS * ss * x2;
    }
    CP_WAIT0();
    __syncthreads();  // w1T staged; coefficients (incl. all reads of raw ss) done

    int q = lane & 3;
    int r = lane >> 2;
    int el0 = wid * 16 + r;
    int rbase = (lane & 7) + ((lane >> 4) & 1) * 8;
    int qbase = (lane >> 3) & 1;

    // ---- GEMM1: h = relu(ea @ w1 + b1), D-frags -> gemm2 A-frags ----
    u32 aH[4][4], aL[4][4];
    {
        float D1[4][8];
#pragma unroll
        for (int bq = 0; bq < 4; bq++)
#pragma unroll
            for (int z = 0; z < 8; z++) D1[bq][z] = 0.0f;

        bool v0 = (e0 + el0) < N_EDGES;
        bool v1 = (e0 + el0 + 8) < N_EDGES;
        const float* row0 = ea + (e0 + el0) * 64;
        const float* row1 = ea + (e0 + el0 + 8) * 64;
        float2 z2 = make_float2(0, 0);

#pragma unroll
        for (int ksin = 0; ksin < 4; ksin++) {
            int c = ksin * 16 + 2 * q;
            float2 x00 = v0 ? *(const float2*)&row0[c] : z2;
            float2 x10 = v1 ? *(const float2*)&row1[c] : z2;
            float2 x01 = v0 ? *(const float2*)&row0[c + 8] : z2;
            float2 x11 = v1 ? *(const float2*)&row1[c + 8] : z2;
            u32 eH[4], eL[4];
            split_pack(x00.x, x00.y, eH[0], eL[0]);
            split_pack(x10.x, x10.y, eH[1], eL[1]);
            split_pack(x01.x, x01.y, eH[2], eL[2]);
            split_pack(x11.x, x11.y, eH[3], eL[3]);

#pragma unroll
            for (int bq = 0; bq < 4; bq++) {
                int rr = bq * 16 + rbase;
                int qq = qbase + ksin * 2;
                u32 ad = sbase + OFF_B + SWX(rr, qq);
                u32 bh0, bh1, bh2, bh3, bl0, bl1, bl2, bl3;
                ldsm4(bh0, bh1, bh2, bh3, ad);
                ldsm4(bl0, bl1, bl2, bl3, ad + 8192);
                mma16816(&D1[bq][0], eH, bh0, bh1);
                mma16816(&D1[bq][4], eH, bh2, bh3);
                mma16816(&D1[bq][0], eH, bl0, bl1);
                mma16816(&D1[bq][4], eH, bl2, bl3);
                mma16816(&D1[bq][0], eL, bh0, bh1);
                mma16816(&D1[bq][4], eL, bh2, bh3);
            }
        }

        // bias + relu + hi/lo split: D1[ks] (n-cols ks*16..+15) == gemm2 k-group ks
#pragma unroll
        for (int ks = 0; ks < 4; ks++) {
            int cb = ks * 16 + 2 * q;
            float2 b01 = *(const float2*)&b1g[cb];
            float2 b89 = *(const float2*)&b1g[cb + 8];
            float d0 = fmaxf(D1[ks][0] + b01.x, 0.0f);
            float d1 = fmaxf(D1[ks][1] + b01.y, 0.0f);
            float d2 = fmaxf(D1[ks][2] + b01.x, 0.0f);
            float d3 = fmaxf(D1[ks][3] + b01.y, 0.0f);
            float d4 = fmaxf(D1[ks][4] + b89.x, 0.0f);
            float d5 = fmaxf(D1[ks][5] + b89.y, 0.0f);
            float d6 = fmaxf(D1[ks][6] + b89.x, 0.0f);
            float d7 = fmaxf(D1[ks][7] + b89.y, 0.0f);
            split_pack(d0, d1, aH[ks][0], aL[ks][0]);
            split_pack(d2, d3, aH[ks][1], aL[ks][1]);
            split_pack(d4, d5, aH[ks][2], aL[ks][2]);
            split_pack(d6, d7, aH[ks][3], aL[ks][3]);
        }
    }
    if (tid < 128) shs[tid * 4] = shs[tid * 4] * (1.0f / INV_SQRT3);  // fac for t=0
    __syncthreads();  // all warps done with w1T(buf0) + fac visible

    // prologue: issue B slices 0,1,2 into bufs 1,2,3 (3 commit groups)
#pragma unroll
    for (int ns = 0; ns < 3; ns++) {
        const char* bhp = (const char*)g_BThi + ns * 8192;
        const char* blp = (const char*)g_BTlo + ns * 8192;
        u32 dbase = sbase + OFF_B + ((ns + 1) & 3) * 16384;
#pragma unroll 1
        for (int idx = tid; idx < 1024; idx += 256) {
            int half = idx >> 9, rem = idx & 511;
            int rr = rem >> 3, qq = rem & 7;
            cpasync16(dbase + half * 8192 + SWX(rr, qq),
                      (half ? blp : bhp) + rr * 128 + qq * 16);
        }
        CP_COMMIT();
    }

    float accS[2][4], accR[2][4], accV[2][4][3];
#pragma unroll
    for (int m = 0; m < 2; m++)
#pragma unroll
        for (int s = 0; s < 4; s++) {
            accS[m][s] = 0; accR[m][s] = 0;
            accV[m][s][0] = 0; accV[m][s][1] = 0; accV[m][s][2] = 0;
        }

#pragma unroll 1
    for (int sl = 0; sl < 16; sl++) {
        int t = sl >> 2, g = sl & 3;
        if (sl < 14) CP_WAIT2();
        else if (sl == 14) CP_WAIT1();
        else CP_WAIT0();
        __syncthreads();  // slice sl ready; all warps done with slice sl-1
        if (sl < 13) {
            int ns = sl + 3;
            const char* bhp = (const char*)g_BThi + ns * 8192;
            const char* blp = (const char*)g_BTlo + ns * 8192;
            u32 dbase = sbase + OFF_B + ((ns + 1) & 3) * 16384;
#pragma unroll 1
            for (int idx = tid; idx < 1024; idx += 256) {
                int half = idx >> 9, rem = idx & 511;
                int rr = rem >> 3, qq = rem & 7;
                cpasync16(dbase + half * 8192 + SWX(rr, qq),
                          (half ? blp : bhp) + rr * 128 + qq * 16);
            }
            CP_COMMIT();
        }

        u32 Bb = sbase + OFF_B + ((sl + 1) & 3) * 16384;

#pragma unroll
        for (int bq = 0; bq < 4; bq++) {
            int rrB = bq * 16 + rbase;
            float d[8];
#pragma unroll
            for (int z = 0; z < 8; z++) d[z] = 0.0f;

#pragma unroll
            for (int ks = 0; ks < 4; ks++) {
                int qqB = qbase + ks * 2;
                u32 ad = Bb + SWX(rrB, qqB);
                u32 bh0, bh1, bh2, bh3, bl0, bl1, bl2, bl3;
                ldsm4(bh0, bh1, bh2, bh3, ad);
                ldsm4(bl0, bl1, bl2, bl3, ad + 8192);
                mma16816(&d[0], aH[ks], bh0, bh1);
                mma16816(&d[4], aH[ks], bh2, bh3);
                mma16816(&d[0], aH[ks], bl0, bl1);
                mma16816(&d[4], aH[ks], bl2, bl3);
                mma16816(&d[0], aL[ks], bh0, bh1);
                mma16816(&d[4], aL[ks], bh2, bh3);
            }

            // contraction: i = 4g + bq is lane-invariant for this group
            int i = g * 4 + bq;
            int colb = g * 64 + bq * 16 + 2 * q;
            if (t < 3) {
                float cv0, cv1;
                if (t == 0) {
                    cv0 = cX[i * 128 + el0] * shs[el0 * 4];
                    cv1 = cX[i * 128 + el0 + 8] * shs[(el0 + 8) * 4];
                } else if (t == 1) {
                    cv0 = cB[i * 128 + el0];
                    cv1 = cB[i * 128 + el0 + 8];
                } else {
                    cv0 = cX[i * 128 + el0];
                    cv1 = cX[i * 128 + el0 + 8];
                }
                float (*acc)[4] = (t == 2) ? accR : accS;
#pragma unroll
                for (int f = 0; f < 2; f++) {
                    float bb0 = b2s[t * 256 + colb + f * 8];
                    float bb1 = b2s[t * 256 + colb + f * 8 + 1];
                    acc[0][f * 2 + 0] += cv0 * (d[f * 4 + 0] + bb0);
                    acc[0][f * 2 + 1] += cv0 * (d[f * 4 + 1] + bb1);
                    acc[1][f * 2 + 0] += cv1 * (d[f * 4 + 2] + bb0);
                    acc[1][f * 2 + 1] += cv1 * (d[f * 4 + 3] + bb1);
                }
            } else {
                float cd0[3], cd1[3];
#pragma unroll
                for (int mm = 0; mm < 3; mm++) {
                    cd0[mm] = cD[(mm * 16 + i) * 128 + el0];
                    cd1[mm] = cD[(mm * 16 + i) * 128 + el0 + 8];
                }
#pragma unroll
                for (int f = 0; f < 2; f++) {
                    float bb0 = b2s[768 + colb + f * 8];
                    float bb1 = b2s[768 + colb + f * 8 + 1];
                    float w00 = d[f * 4 + 0] + bb0, w01 = d[f * 4 + 1] + bb1;
                    float w10 = d[f * 4 + 2] + bb0, w11 = d[f * 4 + 3] + bb1;
#pragma unroll
                    for (int mm = 0; mm < 3; mm++) {
                        accV[0][f * 2 + 0][mm] += cd0[mm] * w00;
                        accV[0][f * 2 + 1][mm] += cd0[mm] * w01;
                        accV[1][f * 2 + 0][mm] += cd1[mm] * w10;
                        accV[1][f * 2 + 1][mm] += cd1[mm] * w11;
                    }
                }
            }
        }
    }

    // scatter
#pragma unroll
    for (int m = 0; m < 2; m++) {
        int el = el0 + 8 * m;
        if (e0 + el < N_EDGES) {
            int src = srcs[el];
            float s1 = shs[el * 4 + 1], s2 = shs[el * 4 + 2], s3 = shs[el * 4 + 3];
#pragma unroll
            for (int sidx = 0; sidx < 4; sidx++) {
                int k = ((sidx >> 1) << 3) + 2 * q + (sidx & 1);
                atomicAdd(&g_agg[src * 64 + k], accS[m][sidx]);
                float rv = accR[m][sidx];
                atomicAdd(&g_agg[src * 64 + 16 + k * 3 + 0], accV[m][sidx][0] + s1 * rv);
                atomicAdd(&g_agg[src * 64 + 16 + k * 3 + 1], accV[m][sidx][1] + s2 * rv);
                atomicAdd(&g_agg[src * 64 + 16 + k * 3 + 2], accV[m][sidx][2] + s3 * rv);
            }
            if (q == 0) atomicAdd(&g_cnt[src], 1.0f);
        }
    }
}

// ---------------- kernel 2: mean + residual + BN stats (+invariant restore) ----------------
__global__ __launch_bounds__(256) void k_stats(const float* __restrict__ node_attr) {
    __shared__ float sstat[48];
    int tid = threadIdx.x;
    if (tid < 48) sstat[tid] = 0.0f;
    __syncthreads();

    int n = blockIdx.x * 16 + (tid >> 4);  // grid covers exactly N_NODES
    int q = tid & 15;
    float cnt = g_cnt[n];
    float inv = 1.0f / fmaxf(cnt, 1.0f);
    float4 ag = *(const float4*)&g_agg[n * 64 + q * 4];
    // restore invariant: zero what we read (exclusive 16B per thread; g_cnt shared)
    *(float4*)&g_agg[n * 64 + q * 4] = make_float4(0, 0, 0, 0);
    __syncwarp();
    if (q == 0) g_cnt[n] = 0.0f;

    float4 na = *(const float4*)&node_attr[n * 64 + q * 4];
    float o[4] = {fmaf(ag.x, inv, na.x), fmaf(ag.y, inv, na.y),
                  fmaf(ag.z, inv, na.z), fmaf(ag.w, inv, na.w)};
    *(float4*)&g_out[n * 64 + q * 4] = make_float4(o[0], o[1], o[2], o[3]);
    if (q < 4) {
#pragma unroll
        for (int t = 0; t < 4; t++) {
            atomicAdd(&sstat[q * 4 + t], o[t]);
            atomicAdd(&sstat[16 + q * 4 + t], o[t] * o[t]);
        }
    } else {
#pragma unroll
        for (int t = 0; t < 4; t++) {
            int k = (q * 4 + t - 16) / 3;
            atomicAdd(&sstat[32 + k], o[t] * o[t]);
        }
    }
    __syncthreads();
    if (tid < 48) atomicAdd(&g_stats[tid], sstat[tid]);
}

// ---------------- kernel 3: normalize (BN finalize folded in) ----------------
__global__ __launch_bounds__(256) void k_norm(const float* __restrict__ bn_weight,
                                              const float* __restrict__ bn_bias,
                                              float* __restrict__ out) {
    __shared__ float prm[48];
    int tid = threadIdx.x;
    if (tid < 16) {
        float mean = g_stats[tid] * (1.0f / N_NODES);
        float var = g_stats[16 + tid] * (1.0f / N_NODES) - mean * mean;
        prm[tid] = mean;
        prm[16 + tid] = bn_weight[tid] * rsqrtf(var + BN_EPS);
        float fn = g_stats[32 + tid] * (1.0f / (3.0f * N_NODES));
        prm[32 + tid] = bn_weight[16 + tid] * rsqrtf(fn + BN_EPS);
    }
    __syncthreads();

    int idx = blockIdx.x * 256 + tid;  // grid covers exactly N_NODES*64
    int f = idx & 63;
    float o = g_out[idx];
    if (f < 16)
        out[idx] = (o - prm[f]) * prm[16 + f] + bn_bias[f];
    else
        out[idx] = o * prm[32 + (f - 16) / 3];
}

// ---------------- launch ----------------
extern "C" void kernel_launch(void* const* d_in, const int* in_sizes, int n_in,
                              void* d_out, int out_size) {
    const float* node_attr = (const float*)d_in[0];
    const float* edge_attr = (const float*)d_in[1];
    const float* edge_sh = (const float*)d_in[2];
    const float* w1 = (const float*)d_in[3];
    const float* b1 = (const float*)d_in[4];
    const float* w2 = (const float*)d_in[5];
    const float* b2 = (const float*)d_in[6];
    const float* bnw = (const float*)d_in[7];
    const float* bnb = (const float*)d_in[8];
    const int* eidx = (const int*)d_in[9];
    float* out = (float*)d_out;

    cudaFuncSetAttribute(k_tp, cudaFuncAttributeMaxDynamicSharedMemorySize, SMEM_TP);

    k_prep<<<128, 256>>>(w2, w1);
    k_tp<<<(N_EDGES + 127) / 128, 256, SMEM_TP>>>(node_attr, edge_sh, b2, eidx,
                                                  edge_attr, b1);
    k_stats<<<N_NODES / 16, 256>>>(node_attr);
    k_norm<<<(N_NODES * 64) / 256, 256>>>(bnw, bnb, out);
}

// round 13
// speedup vs baseline: 1.0769x; 1.0769x over previous
#include <cuda_runtime.h>
#include <cuda_bf16.h>

#define N_NODES 50000
#define N_EDGES 200000
#define MUL 16
#define ALPHA 0.17677669529663687f
#define INV_SQRT3 0.5773502691896258f
#define AIS (ALPHA * INV_SQRT3)
#define BN_EPS 1e-5f

typedef unsigned long long ull;
typedef unsigned int u32;

// ---------------- mma / ldmatrix / cp.async (baseline PTX, no 'a' gates) ----------------
__device__ __forceinline__ u32 smem_u32(const void* p) {
    u32 a;
    asm("{ .reg .u64 t; cvta.to.shared.u64 t, %1; cvt.u32.u64 %0, t; }" : "=r"(a) : "l"(p));
    return a;
}
__device__ __forceinline__ void ldsm4(u32& r0, u32& r1, u32& r2, u32& r3, u32 addr) {
    asm volatile("ldmatrix.sync.aligned.m8n8.x4.shared.b16 {%0,%1,%2,%3}, [%4];"
                 : "=r"(r0), "=r"(r1), "=r"(r2), "=r"(r3) : "r"(addr));
}
__device__ __forceinline__ void mma16816(float* d, const u32* a, u32 b0, u32 b1) {
    asm volatile(
        "mma.sync.aligned.m16n8k16.row.col.f32.bf16.bf16.f32 "
        "{%0,%1,%2,%3}, {%4,%5,%6,%7}, {%8,%9}, {%0,%1,%2,%3};"
        : "+f"(d[0]), "+f"(d[1]), "+f"(d[2]), "+f"(d[3])
        : "r"(a[0]), "r"(a[1]), "r"(a[2]), "r"(a[3]), "r"(b0), "r"(b1));
}
__device__ __forceinline__ void cpasync16(u32 dst, const void* src) {
    asm volatile("cp.async.ca.shared.global [%0], [%1], 16;" :: "r"(dst), "l"(src) : "memory");
}
#define CP_COMMIT() asm volatile("cp.async.commit_group;" ::: "memory")
#define CP_WAIT0() asm volatile("cp.async.wait_group 0;" ::: "memory")

// pack two fp32 -> bf16x2 hi/lo split
__device__ __forceinline__ void split_pack(float va, float vb, u32& hi, u32& lo) {
    __nv_bfloat16 ha = __float2bfloat16(va), hb = __float2bfloat16(vb);
    float la = va - __bfloat162float(ha), lb = vb - __bfloat162float(hb);
    __nv_bfloat162 hp, lp;
    hp.x = ha; hp.y = hb;
    lp.x = __float2bfloat16(la); lp.y = __float2bfloat16(lb);
    hi = *(u32*)&hp;
    lo = *(u32*)&lp;
}

// ---------------- scratch ----------------
__device__ __align__(16) __nv_bfloat16 g_BThi[1024 * 64];
__device__ __align__(16) __nv_bfloat16 g_BTlo[1024 * 64];
__device__ __align__(16) __nv_bfloat16 g_W1Thi[64 * 64];
__device__ __align__(16) __nv_bfloat16 g_W1Tlo[64 * 64];
__device__ float g_agg[N_NODES * 64];   // zero on first run (BSS); restored by k_stats
__device__ float g_cnt[N_NODES];        // same invariant
__device__ float g_out[N_NODES * 64];
__device__ float g_stats[48];

// ---------------- kernel 0: prep (zero g_stats + split w2^T and w1^T) ----------------
__global__ void k_prep(const float* __restrict__ w2, const float* __restrict__ w1) {
    int idx = blockIdx.x * blockDim.x + threadIdx.x;
    int stride = gridDim.x * blockDim.x;
    if (idx < 48) g_stats[idx] = 0.0f;

    // w2 split: g_BT[c][j] = split(w2[j][c])
    for (int i = idx; i < 65536; i += stride) {
        int j = i >> 10, c = i & 1023;
        float v = w2[i];
        __nv_bfloat16 hi = __float2bfloat16(v);
        g_BThi[c * 64 + j] = hi;
        g_BTlo[c * 64 + j] = __float2bfloat16(v - __bfloat162float(hi));
    }
    // w1 split: g_W1T[c][f] = split(w1[f][c])
    if (idx < 4096) {
        int f = idx >> 6, c = idx & 63;
        float v = w1[idx];
        __nv_bfloat16 hi = __float2bfloat16(v);
        g_W1Thi[c * 64 + f] = hi;
        g_W1Tlo[c * 64 + f] = __float2bfloat16(v - __bfloat162float(hi));
    }
}

// ---------------- kernel 1: fused GEMM1 + GEMM2 + TP + scatter (R11 layout) ----------------
// 256 threads, 128 edges/block, 2 blocks/SM, warp owns 16 edges.
// Prologue: h = relu(ea@w1+b1) via HMMA, D-frags reused directly as gemm2 A-frags
// (bf16 hi/lo split in registers). B: 144B-padded tiles, double-buffered cp.async.
#define OFF_AB 0            // 36864: w1T staging (18432), then B dbl buf (2 x 18432)
#define OFF_CA 36864
#define OFF_CB 45312
#define OFF_CX 53760
#define OFF_CD 62208
#define OFF_B2 87552
#define OFF_SHS 91648
#define SMEM_TP 93696

__global__ __launch_bounds__(256, 2) void k_tp(const float* __restrict__ node_attr,
                                               const float* __restrict__ edge_sh,
                                               const float* __restrict__ b2,
                                               const int* __restrict__ edge_index,
                                               const float* __restrict__ ea,
                                               const float* __restrict__ b1g) {
    extern __shared__ __align__(16) char smem[];
    float* cA = (float*)(smem + OFF_CA);
    float* cB = (float*)(smem + OFF_CB);
    float* cX = (float*)(smem + OFF_CX);
    float* cD = (float*)(smem + OFF_CD);
    float* b2s = (float*)(smem + OFF_B2);
    float* shs = (float*)(smem + OFF_SHS);
    __shared__ int srcs[128], dsts[128];

    int tid = threadIdx.x;
    int lane = tid & 31;
    int wid = tid >> 5;
    int e0 = blockIdx.x * 128;
    u32 sbase = smem_u32(smem);

    if (tid < 128) {
        int e = e0 + tid;
        bool val = e < N_EDGES;
        float4 sh = val ? ((const float4*)edge_sh)[e] : make_float4(0, 0, 0, 0);
        *(float4*)&shs[tid * 4] = sh;
        srcs[tid] = val ? edge_index[e] : 0;
        dsts[tid] = val ? edge_index[N_EDGES + e] : -1;
    }
    for (int idx = tid; idx < 1024; idx += 256) b2s[idx] = b2[idx];
    __syncthreads();

    // stage w1T hi/lo into OFF_AB (rows padded to 144B), via cp.async
#pragma unroll 1
    for (int idx = tid; idx < 1024; idx += 256) {
        int half = idx >> 9, rem = idx & 511;
        int rr = rem >> 3, qq = rem & 7;
        const char* srcb = (const char*)(half ? g_W1Tlo : g_W1Thi);
        cpasync16(sbase + OFF_AB + half * 9216 + rr * 144 + qq * 16,
                  srcb + rr * 128 + qq * 16);
    }
    CP_COMMIT();

    // coefficients [i][132e] (overlaps w1T copy)
    for (int idx = tid; idx < 2048; idx += 256) {
        int e = idx >> 4, i = idx & 15;
        int d = dsts[e];
        float ss = shs[e * 4], s1 = shs[e * 4 + 1], s2 = shs[e * 4 + 2], s3 = shs[e * 4 + 3];
        float xs = 0, x0 = 0, x1 = 0, x2 = 0;
        if (d >= 0) {
            xs = node_attr[d * 64 + i];
            const float* xp = &node_attr[d * 64 + 16 + 3 * i];
            x0 = xp[0]; x1 = xp[1]; x2 = xp[2];
        }
        cA[i * 132 + e] = ALPHA * ss * xs;
        cX[i * 132 + e] = AIS * xs;
        cB[i * 132 + e] = AIS * (x0 * s1 + x1 * s2 + x2 * s3);
        cD[(0 * 16 + i) * 132 + e] = AIS * ss * x0;
        cD[(1 * 16 + i) * 132 + e] = AIS * ss * x1;
        cD[(2 * 16 + i) * 132 + e] = AIS * ss * x2;
    }
    CP_WAIT0();
    __syncthreads();  // w1T staged; coefficients visible

    int q = lane & 3;
    int r = lane >> 2;
    int el0 = wid * 16 + r;
    u32 laneB = (u32)(((lane & 7) + ((lane >> 4) & 1) * 8) * 144 + ((lane >> 3) & 1) * 16);

    // ---- GEMM1: h = relu(ea @ w1 + b1), D-frags -> gemm2 A-frags ----
    u32 aH[4][4], aL[4][4];
    {
        float D1[4][8];
#pragma unroll
        for (int bq = 0; bq < 4; bq++)
#pragma unroll
            for (int z = 0; z < 8; z++) D1[bq][z] = 0.0f;

        bool v0 = (e0 + el0) < N_EDGES;
        bool v1 = (e0 + el0 + 8) < N_EDGES;
        const float* row0 = ea + (e0 + el0) * 64;
        const float* row1 = ea + (e0 + el0 + 8) * 64;
        float2 z2 = make_float2(0, 0);

#pragma unroll
        for (int ksin = 0; ksin < 4; ksin++) {
            int c = ksin * 16 + 2 * q;
            float2 x00 = v0 ? *(const float2*)&row0[c] : z2;
            float2 x10 = v1 ? *(const float2*)&row1[c] : z2;
            float2 x01 = v0 ? *(const float2*)&row0[c + 8] : z2;
            float2 x11 = v1 ? *(const float2*)&row1[c + 8] : z2;
            u32 eH[4], eL[4];
            split_pack(x00.x, x00.y, eH[0], eL[0]);
            split_pack(x10.x, x10.y, eH[1], eL[1]);
            split_pack(x01.x, x01.y, eH[2], eL[2]);
            split_pack(x11.x, x11.y, eH[3], eL[3]);

#pragma unroll
            for (int bq = 0; bq < 4; bq++) {
                u32 bh0, bh1, bh2, bh3, bl0, bl1, bl2, bl3;
                u32 ad = sbase + OFF_AB + laneB + bq * 2304 + ksin * 32;
                ldsm4(bh0, bh1, bh2, bh3, ad);
                ldsm4(bl0, bl1, bl2, bl3, ad + 9216);
                mma16816(&D1[bq][0], eH, bh0, bh1);
                mma16816(&D1[bq][4], eH, bh2, bh3);
                mma16816(&D1[bq][0], eH, bl0, bl1);
                mma16816(&D1[bq][4], eH, bl2, bl3);
                mma16816(&D1[bq][0], eL, bh0, bh1);
                mma16816(&D1[bq][4], eL, bh2, bh3);
            }
        }

        // bias + relu + hi/lo split: D1[ks] group (n-cols ks*16..+15) == gemm2 k-group ks
#pragma unroll
        for (int ks = 0; ks < 4; ks++) {
            int cb = ks * 16 + 2 * q;
            float2 b01 = *(const float2*)&b1g[cb];
            float2 b89 = *(const float2*)&b1g[cb + 8];
            float d0 = fmaxf(D1[ks][0] + b01.x, 0.0f);
            float d1 = fmaxf(D1[ks][1] + b01.y, 0.0f);
            float d2 = fmaxf(D1[ks][2] + b01.x, 0.0f);
            float d3 = fmaxf(D1[ks][3] + b01.y, 0.0f);
            float d4 = fmaxf(D1[ks][4] + b89.x, 0.0f);
            float d5 = fmaxf(D1[ks][5] + b89.y, 0.0f);
            float d6 = fmaxf(D1[ks][6] + b89.x, 0.0f);
            float d7 = fmaxf(D1[ks][7] + b89.y, 0.0f);
            split_pack(d0, d1, aH[ks][0], aL[ks][0]);
            split_pack(d2, d3, aH[ks][1], aL[ks][1]);
            split_pack(d4, d5, aH[ks][2], aL[ks][2]);
            split_pack(d6, d7, aH[ks][3], aL[ks][3]);
        }
    }
    __syncthreads();  // all warps done reading w1T before B overwrites

    // issue B slice 0 into buffer 0
#pragma unroll 1
    for (int idx = tid; idx < 1024; idx += 256) {
        int half = idx >> 9, rem = idx & 511;
        int rr = rem >> 3, qq = rem & 7;
        const char* srcb = (const char*)(half ? g_BTlo : g_BThi);
        cpasync16(sbase + OFF_AB + half * 9216 + rr * 144 + qq * 16,
                  srcb + rr * 128 + qq * 16);
    }
    CP_COMMIT();

    float accS[2][4], accR[2][4], accV[2][4][3];
#pragma unroll
    for (int m = 0; m < 2; m++)
#pragma unroll
        for (int s = 0; s < 4; s++) {
            accS[m][s] = 0; accR[m][s] = 0;
            accV[m][s][0] = 0; accV[m][s][1] = 0; accV[m][s][2] = 0;
        }

#pragma unroll 1
    for (int sl = 0; sl < 16; sl++) {
        int t = sl >> 2, g = sl & 3;
        int buf = sl & 1;
        CP_WAIT0();
        __syncthreads();  // slice sl ready; compute(sl-1) fully done
        if (sl < 15) {
            int nb = (sl + 1) & 1;
            const char* bhp = (const char*)&g_BThi[(sl + 1) * 64 * 64];
            const char* blp = (const char*)&g_BTlo[(sl + 1) * 64 * 64];
#pragma unroll 1
            for (int idx = tid; idx < 1024; idx += 256) {
                int half = idx >> 9, rem = idx & 511;
                int rr = rem >> 3, qq = rem & 7;
                cpasync16(sbase + OFF_AB + nb * 18432 + half * 9216 + rr * 144 + qq * 16,
                          (half ? blp : bhp) + rr * 128 + qq * 16);
            }
            CP_COMMIT();
        }

        u32 bHbase = sbase + OFF_AB + buf * 18432 + laneB;
        u32 bLbase = bHbase + 9216;

#pragma unroll
        for (int bq = 0; bq < 4; bq++) {
            float d[8];
#pragma unroll
            for (int z = 0; z < 8; z++) d[z] = 0.0f;

#pragma unroll
            for (int ks = 0; ks < 4; ks++) {
                u32 bh0, bh1, bh2, bh3, bl0, bl1, bl2, bl3;
                ldsm4(bh0, bh1, bh2, bh3, bHbase + bq * 2304 + ks * 32);
                ldsm4(bl0, bl1, bl2, bl3, bLbase + bq * 2304 + ks * 32);
                mma16816(&d[0], aH[ks], bh0, bh1);
                mma16816(&d[4], aH[ks], bh2, bh3);
                mma16816(&d[0], aH[ks], bl0, bl1);
                mma16816(&d[4], aH[ks], bl2, bl3);
                mma16816(&d[0], aL[ks], bh0, bh1);
                mma16816(&d[4], aL[ks], bh2, bh3);
            }

            // contraction: i = 4g + bq is lane-invariant for this group
            int i = g * 4 + bq;
            int colb = g * 64 + bq * 16 + 2 * q;
            if (t < 3) {
                const float* cp = (t == 0) ? cA : (t == 1) ? cB : cX;
                float cv0 = cp[i * 132 + el0];
                float cv1 = cp[i * 132 + el0 + 8];
                float (*acc)[4] = (t == 2) ? accR : accS;
#pragma unroll
                for (int f = 0; f < 2; f++) {
                    float bb0 = b2s[t * 256 + colb + f * 8];
                    float bb1 = b2s[t * 256 + colb + f * 8 + 1];
                    acc[0][f * 2 + 0] += cv0 * (d[f * 4 + 0] + bb0);
                    acc[0][f * 2 + 1] += cv0 * (d[f * 4 + 1] + bb1);
                    acc[1][f * 2 + 0] += cv1 * (d[f * 4 + 2] + bb0);
                    acc[1][f * 2 + 1] += cv1 * (d[f * 4 + 3] + bb1);
                }
            } else {
                float cd0[3], cd1[3];
#pragma unroll
                for (int mm = 0; mm < 3; mm++) {
                    cd0[mm] = cD[(mm * 16 + i) * 132 + el0];
                    cd1[mm] = cD[(mm * 16 + i) * 132 + el0 + 8];
                }
#pragma unroll
                for (int f = 0; f < 2; f++) {
                    float bb0 = b2s[768 + colb + f * 8];
                    float bb1 = b2s[768 + colb + f * 8 + 1];
                    float w00 = d[f * 4 + 0] + bb0, w01 = d[f * 4 + 1] + bb1;
                    float w10 = d[f * 4 + 2] + bb0, w11 = d[f * 4 + 3] + bb1;
#pragma unroll
                    for (int mm = 0; mm < 3; mm++) {
                        accV[0][f * 2 + 0][mm] += cd0[mm] * w00;
                        accV[0][f * 2 + 1][mm] += cd0[mm] * w01;
                        accV[1][f * 2 + 0][mm] += cd1[mm] * w10;
                        accV[1][f * 2 + 1][mm] += cd1[mm] * w11;
                    }
                }
            }
        }
    }

    // scatter
#pragma unroll
    for (int m = 0; m < 2; m++) {
        int el = el0 + 8 * m;
        if (e0 + el < N_EDGES) {
            int src = srcs[el];
            float s1 = shs[el * 4 + 1], s2 = shs[el * 4 + 2], s3 = shs[el * 4 + 3];
#pragma unroll
            for (int sidx = 0; sidx < 4; sidx++) {
                int k = ((sidx >> 1) << 3) + 2 * q + (sidx & 1);
                atomicAdd(&g_agg[src * 64 + k], accS[m][sidx]);
                float rv = accR[m][sidx];
                atomicAdd(&g_agg[src * 64 + 16 + k * 3 + 0], accV[m][sidx][0] + s1 * rv);
                atomicAdd(&g_agg[src * 64 + 16 + k * 3 + 1], accV[m][sidx][1] + s2 * rv);
                atomicAdd(&g_agg[src * 64 + 16 + k * 3 + 2], accV[m][sidx][2] + s3 * rv);
            }
            if (q == 0) atomicAdd(&g_cnt[src], 1.0f);
        }
    }
}

// ---------------- kernel 2: mean + residual + BN stats (+invariant restore) ----------------
__global__ __launch_bounds__(256) void k_stats(const float* __restrict__ node_attr) {
    __shared__ float sstat[48];
    int tid = threadIdx.x;
    if (tid < 48) sstat[tid] = 0.0f;
    __syncthreads();

    int n = blockIdx.x * 16 + (tid >> 4);  // grid covers exactly N_NODES
    int q = tid & 15;
    float cnt = g_cnt[n];
    float inv = 1.0f / fmaxf(cnt, 1.0f);
    float4 ag = *(const float4*)&g_agg[n * 64 + q * 4];
    // restore zero-invariant: each thread zeroes the exclusive 16B it consumed;
    // g_cnt word shared by 16 threads -> one writer after syncwarp
    *(float4*)&g_agg[n * 64 + q * 4] = make_float4(0, 0, 0, 0);
    __syncwarp();
    if (q == 0) g_cnt[n] = 0.0f;

    float4 na = *(const float4*)&node_attr[n * 64 + q * 4];
    float o[4] = {fmaf(ag.x, inv, na.x), fmaf(ag.y, inv, na.y),
                  fmaf(ag.z, inv, na.z), fmaf(ag.w, inv, na.w)};
    *(float4*)&g_out[n * 64 + q * 4] = make_float4(o[0], o[1], o[2], o[3]);
    if (q < 4) {
#pragma unroll
        for (int t = 0; t < 4; t++) {
            atomicAdd(&sstat[q * 4 + t], o[t]);
            atomicAdd(&sstat[16 + q * 4 + t], o[t] * o[t]);
        }
    } else {
#pragma unroll
        for (int t = 0; t < 4; t++) {
            int k = (q * 4 + t - 16) / 3;
            atomicAdd(&sstat[32 + k], o[t] * o[t]);
        }
    }
    __syncthreads();
    if (tid < 48) atomicAdd(&g_stats[tid], sstat[tid]);
}

// ---------------- kernel 3: normalize (BN finalize folded in) ----------------
__global__ __launch_bounds__(256) void k_norm(const float* __restrict__ bn_weight,
                                              const float* __restrict__ bn_bias,
                                              float* __restrict__ out) {
    __shared__ float prm[48];
    int tid = threadIdx.x;
    if (tid < 16) {
        float mean = g_stats[tid] * (1.0f / N_NODES);
        float var = g_stats[16 + tid] * (1.0f / N_NODES) - mean * mean;
        prm[tid] = mean;
        prm[16 + tid] = bn_weight[tid] * rsqrtf(var + BN_EPS);
        float fn = g_stats[32 + tid] * (1.0f / (3.0f * N_NODES));
        prm[32 + tid] = bn_weight[16 + tid] * rsqrtf(fn + BN_EPS);
    }
    __syncthreads();

    int idx = blockIdx.x * 256 + tid;  // grid covers exactly N_NODES*64
    int f = idx & 63;
    float o = g_out[idx];
    if (f < 16)
        out[idx] = (o - prm[f]) * prm[16 + f] + bn_bias[f];
    else
        out[idx] = o * prm[32 + (f - 16) / 3];
}

// ---------------- launch ----------------
extern "C" void kernel_launch(void* const* d_in, const int* in_sizes, int n_in,
                              void* d_out, int out_size) {
    const float* node_attr = (const float*)d_in[0];
    const float* edge_attr = (const float*)d_in[1];
    const float* edge_sh = (const float*)d_in[2];
    const float* w1 = (const float*)d_in[3];
    const float* b1 = (const float*)d_in[4];
    const float* w2 = (const float*)d_in[5];
    const float* b2 = (const float*)d_in[6];
    const float* bnw = (const float*)d_in[7];
    const float* bnb = (const float*)d_in[8];
    const int* eidx = (const int*)d_in[9];
    float* out = (float*)d_out;

    cudaFuncSetAttribute(k_tp, cudaFuncAttributeMaxDynamicSharedMemorySize, SMEM_TP);

    k_prep<<<128, 256>>>(w2, w1);
    k_tp<<<(N_EDGES + 127) / 128, 256, SMEM_TP>>>(node_attr, edge_sh, b2, eidx,
                                                  edge_attr, b1);
    k_stats<<<N_NODES / 16, 256>>>(node_attr);
    k_norm<<<(N_NODES * 64) / 256, 256>>>(bnw, bnb, out);
}

// round 14
// speedup vs baseline: 1.1251x; 1.0447x over previous
#include <cuda_runtime.h>
#include <cuda_bf16.h>

#define N_NODES 50000
#define N_EDGES 200000
#define MUL 16
#define ALPHA 0.17677669529663687f
#define INV_SQRT3 0.5773502691896258f
#define AIS (ALPHA * INV_SQRT3)
#define BN_EPS 1e-5f

typedef unsigned long long ull;
typedef unsigned int u32;

// ---------------- mma / ldmatrix / cp.async (baseline PTX, no 'a' gates) ----------------
__device__ __forceinline__ u32 smem_u32(const void* p) {
    u32 a;
    asm("{ .reg .u64 t; cvta.to.shared.u64 t, %1; cvt.u32.u64 %0, t; }" : "=r"(a) : "l"(p));
    return a;
}
__device__ __forceinline__ void ldsm4(u32& r0, u32& r1, u32& r2, u32& r3, u32 addr) {
    asm volatile("ldmatrix.sync.aligned.m8n8.x4.shared.b16 {%0,%1,%2,%3}, [%4];"
                 : "=r"(r0), "=r"(r1), "=r"(r2), "=r"(r3) : "r"(addr));
}
__device__ __forceinline__ void mma16816(float* d, const u32* a, u32 b0, u32 b1) {
    asm volatile(
        "mma.sync.aligned.m16n8k16.row.col.f32.bf16.bf16.f32 "
        "{%0,%1,%2,%3}, {%4,%5,%6,%7}, {%8,%9}, {%0,%1,%2,%3};"
        : "+f"(d[0]), "+f"(d[1]), "+f"(d[2]), "+f"(d[3])
        : "r"(a[0]), "r"(a[1]), "r"(a[2]), "r"(a[3]), "r"(b0), "r"(b1));
}
__device__ __forceinline__ void cpasync16(u32 dst, const void* src) {
    asm volatile("cp.async.ca.shared.global [%0], [%1], 16;" :: "r"(dst), "l"(src) : "memory");
}
#define CP_COMMIT() asm volatile("cp.async.commit_group;" ::: "memory")
#define CP_WAIT0() asm volatile("cp.async.wait_group 0;" ::: "memory")

// vectorized global f32 reduction (PTX 8.1+, sm_90+; 8B-aligned address required)
__device__ __forceinline__ void red2(float* p, float a, float b) {
    asm volatile("red.global.add.v2.f32 [%0], {%1, %2};" :: "l"(p), "f"(a), "f"(b) : "memory");
}

// pack two fp32 -> bf16x2 hi/lo split
__device__ __forceinline__ void split_pack(float va, float vb, u32& hi, u32& lo) {
    __nv_bfloat16 ha = __float2bfloat16(va), hb = __float2bfloat16(vb);
    float la = va - __bfloat162float(ha), lb = vb - __bfloat162float(hb);
    __nv_bfloat162 hp, lp;
    hp.x = ha; hp.y = hb;
    lp.x = __float2bfloat16(la); lp.y = __float2bfloat16(lb);
    hi = *(u32*)&hp;
    lo = *(u32*)&lp;
}

// ---------------- scratch ----------------
__device__ __align__(16) __nv_bfloat16 g_BThi[1024 * 64];
__device__ __align__(16) __nv_bfloat16 g_BTlo[1024 * 64];
__device__ __align__(16) __nv_bfloat16 g_W1Thi[64 * 64];
__device__ __align__(16) __nv_bfloat16 g_W1Tlo[64 * 64];
__device__ __align__(256) float g_agg[N_NODES * 64];  // zero on first run (BSS); restored by k_stats
__device__ float g_cnt[N_NODES];                      // same invariant
__device__ float g_out[N_NODES * 64];
__device__ float g_stats[48];

// ---------------- kernel 0: prep (zero g_stats + split w2^T and w1^T) ----------------
__global__ void k_prep(const float* __restrict__ w2, const float* __restrict__ w1) {
    int idx = blockIdx.x * blockDim.x + threadIdx.x;
    int stride = gridDim.x * blockDim.x;
    if (idx < 48) g_stats[idx] = 0.0f;

    // w2 split: g_BT[c][j] = split(w2[j][c])
    for (int i = idx; i < 65536; i += stride) {
        int j = i >> 10, c = i & 1023;
        float v = w2[i];
        __nv_bfloat16 hi = __float2bfloat16(v);
        g_BThi[c * 64 + j] = hi;
        g_BTlo[c * 64 + j] = __float2bfloat16(v - __bfloat162float(hi));
    }
    // w1 split: g_W1T[c][f] = split(w1[f][c])
    if (idx < 4096) {
        int f = idx >> 6, c = idx & 63;
        float v = w1[idx];
        __nv_bfloat16 hi = __float2bfloat16(v);
        g_W1Thi[c * 64 + f] = hi;
        g_W1Tlo[c * 64 + f] = __float2bfloat16(v - __bfloat162float(hi));
    }
}

// ---------------- kernel 1: fused GEMM1 + GEMM2 + TP + scatter (R11 layout) ----------------
// 256 threads, 128 edges/block, 2 blocks/SM, warp owns 16 edges.
// Prologue: h = relu(ea@w1+b1) via HMMA, D-frags reused directly as gemm2 A-frags.
// B: 144B-padded tiles, double-buffered cp.async. Scatter via red.v2.f32.
#define OFF_AB 0            // 36864: w1T staging (18432), then B dbl buf (2 x 18432)
#define OFF_CA 36864
#define OFF_CB 45312
#define OFF_CX 53760
#define OFF_CD 62208
#define OFF_B2 87552
#define OFF_SHS 91648
#define SMEM_TP 93696

__global__ __launch_bounds__(256, 2) void k_tp(const float* __restrict__ node_attr,
                                               const float* __restrict__ edge_sh,
                                               const float* __restrict__ b2,
                                               const int* __restrict__ edge_index,
                                               const float* __restrict__ ea,
                                               const float* __restrict__ b1g) {
    extern __shared__ __align__(16) char smem[];
    float* cA = (float*)(smem + OFF_CA);
    float* cB = (float*)(smem + OFF_CB);
    float* cX = (float*)(smem + OFF_CX);
    float* cD = (float*)(smem + OFF_CD);
    float* b2s = (float*)(smem + OFF_B2);
    float* shs = (float*)(smem + OFF_SHS);
    __shared__ int srcs[128], dsts[128];

    int tid = threadIdx.x;
    int lane = tid & 31;
    int wid = tid >> 5;
    int e0 = blockIdx.x * 128;
    u32 sbase = smem_u32(smem);

    if (tid < 128) {
        int e = e0 + tid;
        bool val = e < N_EDGES;
        float4 sh = val ? ((const float4*)edge_sh)[e] : make_float4(0, 0, 0, 0);
        *(float4*)&shs[tid * 4] = sh;
        srcs[tid] = val ? edge_index[e] : 0;
        dsts[tid] = val ? edge_index[N_EDGES + e] : -1;
    }
    for (int idx = tid; idx < 1024; idx += 256) b2s[idx] = b2[idx];
    __syncthreads();

    // stage w1T hi/lo into OFF_AB (rows padded to 144B), via cp.async
#pragma unroll 1
    for (int idx = tid; idx < 1024; idx += 256) {
        int half = idx >> 9, rem = idx & 511;
        int rr = rem >> 3, qq = rem & 7;
        const char* srcb = (const char*)(half ? g_W1Tlo : g_W1Thi);
        cpasync16(sbase + OFF_AB + half * 9216 + rr * 144 + qq * 16,
                  srcb + rr * 128 + qq * 16);
    }
    CP_COMMIT();

    // coefficients [i][132e] (overlaps w1T copy)
    for (int idx = tid; idx < 2048; idx += 256) {
        int e = idx >> 4, i = idx & 15;
        int d = dsts[e];
        float ss = shs[e * 4], s1 = shs[e * 4 + 1], s2 = shs[e * 4 + 2], s3 = shs[e * 4 + 3];
        float xs = 0, x0 = 0, x1 = 0, x2 = 0;
        if (d >= 0) {
            xs = node_attr[d * 64 + i];
            const float* xp = &node_attr[d * 64 + 16 + 3 * i];
            x0 = xp[0]; x1 = xp[1]; x2 = xp[2];
        }
        cA[i * 132 + e] = ALPHA * ss * xs;
        cX[i * 132 + e] = AIS * xs;
        cB[i * 132 + e] = AIS * (x0 * s1 + x1 * s2 + x2 * s3);
        cD[(0 * 16 + i) * 132 + e] = AIS * ss * x0;
        cD[(1 * 16 + i) * 132 + e] = AIS * ss * x1;
        cD[(2 * 16 + i) * 132 + e] = AIS * ss * x2;
    }
    CP_WAIT0();
    __syncthreads();  // w1T staged; coefficients visible

    int q = lane & 3;
    int r = lane >> 2;
    int el0 = wid * 16 + r;
    u32 laneB = (u32)(((lane & 7) + ((lane >> 4) & 1) * 8) * 144 + ((lane >> 3) & 1) * 16);

    // ---- GEMM1: h = relu(ea @ w1 + b1), D-frags -> gemm2 A-frags ----
    u32 aH[4][4], aL[4][4];
    {
        float D1[4][8];
#pragma unroll
        for (int bq = 0; bq < 4; bq++)
#pragma unroll
            for (int z = 0; z < 8; z++) D1[bq][z] = 0.0f;

        bool v0 = (e0 + el0) < N_EDGES;
        bool v1 = (e0 + el0 + 8) < N_EDGES;
        const float* row0 = ea + (e0 + el0) * 64;
        const float* row1 = ea + (e0 + el0 + 8) * 64;
        float2 z2 = make_float2(0, 0);

#pragma unroll
        for (int ksin = 0; ksin < 4; ksin++) {
            int c = ksin * 16 + 2 * q;
            float2 x00 = v0 ? *(const float2*)&row0[c] : z2;
            float2 x10 = v1 ? *(const float2*)&row1[c] : z2;
            float2 x01 = v0 ? *(const float2*)&row0[c + 8] : z2;
            float2 x11 = v1 ? *(const float2*)&row1[c + 8] : z2;
            u32 eH[4], eL[4];
            split_pack(x00.x, x00.y, eH[0], eL[0]);
            split_pack(x10.x, x10.y, eH[1], eL[1]);
            split_pack(x01.x, x01.y, eH[2], eL[2]);
            split_pack(x11.x, x11.y, eH[3], eL[3]);

#pragma unroll
            for (int bq = 0; bq < 4; bq++) {
                u32 bh0, bh1, bh2, bh3, bl0, bl1, bl2, bl3;
                u32 ad = sbase + OFF_AB + laneB + bq * 2304 + ksin * 32;
                ldsm4(bh0, bh1, bh2, bh3, ad);
                ldsm4(bl0, bl1, bl2, bl3, ad + 9216);
                mma16816(&D1[bq][0], eH, bh0, bh1);
                mma16816(&D1[bq][4], eH, bh2, bh3);
                mma16816(&D1[bq][0], eH, bl0, bl1);
                mma16816(&D1[bq][4], eH, bl2, bl3);
                mma16816(&D1[bq][0], eL, bh0, bh1);
                mma16816(&D1[bq][4], eL, bh2, bh3);
            }
        }

        // bias + relu + hi/lo split: D1[ks] group (n-cols ks*16..+15) == gemm2 k-group ks
#pragma unroll
        for (int ks = 0; ks < 4; ks++) {
            int cb = ks * 16 + 2 * q;
            float2 b01 = *(const float2*)&b1g[cb];
            float2 b89 = *(const float2*)&b1g[cb + 8];
            float d0 = fmaxf(D1[ks][0] + b01.x, 0.0f);
            float d1 = fmaxf(D1[ks][1] + b01.y, 0.0f);
            float d2 = fmaxf(D1[ks][2] + b01.x, 0.0f);
            float d3 = fmaxf(D1[ks][3] + b01.y, 0.0f);
            float d4 = fmaxf(D1[ks][4] + b89.x, 0.0f);
            float d5 = fmaxf(D1[ks][5] + b89.y, 0.0f);
            float d6 = fmaxf(D1[ks][6] + b89.x, 0.0f);
            float d7 = fmaxf(D1[ks][7] + b89.y, 0.0f);
            split_pack(d0, d1, aH[ks][0], aL[ks][0]);
            split_pack(d2, d3, aH[ks][1], aL[ks][1]);
            split_pack(d4, d5, aH[ks][2], aL[ks][2]);
            split_pack(d6, d7, aH[ks][3], aL[ks][3]);
        }
    }
    __syncthreads();  // all warps done reading w1T before B overwrites

    // issue B slice 0 into buffer 0
#pragma unroll 1
    for (int idx = tid; idx < 1024; idx += 256) {
        int half = idx >> 9, rem = idx & 511;
        int rr = rem >> 3, qq = rem & 7;
        const char* srcb = (const char*)(half ? g_BTlo : g_BThi);
        cpasync16(sbase + OFF_AB + half * 9216 + rr * 144 + qq * 16,
                  srcb + rr * 128 + qq * 16);
    }
    CP_COMMIT();

    float accS[2][4], accR[2][4], accV[2][4][3];
#pragma unroll
    for (int m = 0; m < 2; m++)
#pragma unroll
        for (int s = 0; s < 4; s++) {
            accS[m][s] = 0; accR[m][s] = 0;
            accV[m][s][0] = 0; accV[m][s][1] = 0; accV[m][s][2] = 0;
        }

#pragma unroll 1
    for (int sl = 0; sl < 16; sl++) {
        int t = sl >> 2, g = sl & 3;
        int buf = sl & 1;
        CP_WAIT0();
        __syncthreads();  // slice sl ready; compute(sl-1) fully done
        if (sl < 15) {
            int nb = (sl + 1) & 1;
            const char* bhp = (const char*)&g_BThi[(sl + 1) * 64 * 64];
            const char* blp = (const char*)&g_BTlo[(sl + 1) * 64 * 64];
#pragma unroll 1
            for (int idx = tid; idx < 1024; idx += 256) {
                int half = idx >> 9, rem = idx & 511;
                int rr = rem >> 3, qq = rem & 7;
                cpasync16(sbase + OFF_AB + nb * 18432 + half * 9216 + rr * 144 + qq * 16,
                          (half ? blp : bhp) + rr * 128 + qq * 16);
            }
            CP_COMMIT();
        }

        u32 bHbase = sbase + OFF_AB + buf * 18432 + laneB;
        u32 bLbase = bHbase + 9216;

#pragma unroll
        for (int bq = 0; bq < 4; bq++) {
            float d[8];
#pragma unroll
            for (int z = 0; z < 8; z++) d[z] = 0.0f;

#pragma unroll
            for (int ks = 0; ks < 4; ks++) {
                u32 bh0, bh1, bh2, bh3, bl0, bl1, bl2, bl3;
                ldsm4(bh0, bh1, bh2, bh3, bHbase + bq * 2304 + ks * 32);
                ldsm4(bl0, bl1, bl2, bl3, bLbase + bq * 2304 + ks * 32);
                mma16816(&d[0], aH[ks], bh0, bh1);
                mma16816(&d[4], aH[ks], bh2, bh3);
                mma16816(&d[0], aH[ks], bl0, bl1);
                mma16816(&d[4], aH[ks], bl2, bl3);
                mma16816(&d[0], aL[ks], bh0, bh1);
                mma16816(&d[4], aL[ks], bh2, bh3);
            }

            // contraction: i = 4g + bq is lane-invariant for this group
            int i = g * 4 + bq;
            int colb = g * 64 + bq * 16 + 2 * q;
            if (t < 3) {
                const float* cp = (t == 0) ? cA : (t == 1) ? cB : cX;
                float cv0 = cp[i * 132 + el0];
                float cv1 = cp[i * 132 + el0 + 8];
                float (*acc)[4] = (t == 2) ? accR : accS;
#pragma unroll
                for (int f = 0; f < 2; f++) {
                    float bb0 = b2s[t * 256 + colb + f * 8];
                    float bb1 = b2s[t * 256 + colb + f * 8 + 1];
                    acc[0][f * 2 + 0] += cv0 * (d[f * 4 + 0] + bb0);
                    acc[0][f * 2 + 1] += cv0 * (d[f * 4 + 1] + bb1);
                    acc[1][f * 2 + 0] += cv1 * (d[f * 4 + 2] + bb0);
                    acc[1][f * 2 + 1] += cv1 * (d[f * 4 + 3] + bb1);
                }
            } else {
                float cd0[3], cd1[3];
#pragma unroll
                for (int mm = 0; mm < 3; mm++) {
                    cd0[mm] = cD[(mm * 16 + i) * 132 + el0];
                    cd1[mm] = cD[(mm * 16 + i) * 132 + el0 + 8];
                }
#pragma unroll
                for (int f = 0; f < 2; f++) {
                    float bb0 = b2s[768 + colb + f * 8];
                    float bb1 = b2s[768 + colb + f * 8 + 1];
                    float w00 = d[f * 4 + 0] + bb0, w01 = d[f * 4 + 1] + bb1;
                    float w10 = d[f * 4 + 2] + bb0, w11 = d[f * 4 + 3] + bb1;
#pragma unroll
                    for (int mm = 0; mm < 3; mm++) {
                        accV[0][f * 2 + 0][mm] += cd0[mm] * w00;
                        accV[0][f * 2 + 1][mm] += cd0[mm] * w01;
                        accV[1][f * 2 + 0][mm] += cd1[mm] * w10;
                        accV[1][f * 2 + 1][mm] += cd1[mm] * w11;
                    }
                }
            }
        }
    }

    // scatter: vectorized red.v2.f32 (k pairs {2q,2q+1} and {2q+8,2q+9} are adjacent;
    // their v-blocks are 6 contiguous floats at 16+6q and 16+6q+24; all 8B-aligned)
#pragma unroll
    for (int m = 0; m < 2; m++) {
        int el = el0 + 8 * m;
        if (e0 + el < N_EDGES) {
            int src = srcs[el];
            float s1 = shs[el * 4 + 1], s2 = shs[el * 4 + 2], s3 = shs[el * 4 + 3];
            float* base = &g_agg[src * 64];
            red2(base + 2 * q, accS[m][0], accS[m][1]);
            red2(base + 2 * q + 8, accS[m][2], accS[m][3]);
#pragma unroll
            for (int p = 0; p < 2; p++) {
                float r0 = accR[m][2 * p], r1 = accR[m][2 * p + 1];
                float v0 = accV[m][2 * p][0] + s1 * r0;
                float v1 = accV[m][2 * p][1] + s2 * r0;
                float v2 = accV[m][2 * p][2] + s3 * r0;
                float v3 = accV[m][2 * p + 1][0] + s1 * r1;
                float v4 = accV[m][2 * p + 1][1] + s2 * r1;
                float v5 = accV[m][2 * p + 1][2] + s3 * r1;
                float* vp = base + 16 + 6 * q + 24 * p;
                red2(vp, v0, v1);
                red2(vp + 2, v2, v3);
                red2(vp + 4, v4, v5);
            }
            if (q == 0) atomicAdd(&g_cnt[src], 1.0f);
        }
    }
}

// ---------------- kernel 2: mean + residual + BN stats (+invariant restore) ----------------
__global__ __launch_bounds__(256) void k_stats(const float* __restrict__ node_attr) {
    __shared__ float sstat[48];
    int tid = threadIdx.x;
    if (tid < 48) sstat[tid] = 0.0f;
    __syncthreads();

    int n = blockIdx.x * 16 + (tid >> 4);  // grid covers exactly N_NODES
    int q = tid & 15;
    float cnt = g_cnt[n];
    float inv = 1.0f / fmaxf(cnt, 1.0f);
    float4 ag = *(const float4*)&g_agg[n * 64 + q * 4];
    // restore zero-invariant: each thread zeroes the exclusive 16B it consumed;
    // g_cnt word shared by 16 threads -> one writer after syncwarp
    *(float4*)&g_agg[n * 64 + q * 4] = make_float4(0, 0, 0, 0);
    __syncwarp();
    if (q == 0) g_cnt[n] = 0.0f;

    float4 na = *(const float4*)&node_attr[n * 64 + q * 4];
    float o[4] = {fmaf(ag.x, inv, na.x), fmaf(ag.y, inv, na.y),
                  fmaf(ag.z, inv, na.z), fmaf(ag.w, inv, na.w)};
    *(float4*)&g_out[n * 64 + q * 4] = make_float4(o[0], o[1], o[2], o[3]);
    if (q < 4) {
#pragma unroll
        for (int t = 0; t < 4; t++) {
            atomicAdd(&sstat[q * 4 + t], o[t]);
            atomicAdd(&sstat[16 + q * 4 + t], o[t] * o[t]);
        }
    } else {
#pragma unroll
        for (int t = 0; t < 4; t++) {
            int k = (q * 4 + t - 16) / 3;
            atomicAdd(&sstat[32 + k], o[t] * o[t]);
        }
    }
    __syncthreads();
    if (tid < 48) atomicAdd(&g_stats[tid], sstat[tid]);
}

// ---------------- kernel 3: normalize (BN finalize folded in) ----------------
__global__ __launch_bounds__(256) void k_norm(const float* __restrict__ bn_weight,
                                              const float* __restrict__ bn_bias,
                                              float* __restrict__ out) {
    __shared__ float prm[48];
    int tid = threadIdx.x;
    if (tid < 16) {
        float mean = g_stats[tid] * (1.0f / N_NODES);
        float var = g_stats[16 + tid] * (1.0f / N_NODES) - mean * mean;
        prm[tid] = mean;
        prm[16 + tid] = bn_weight[tid] * rsqrtf(var + BN_EPS);
        float fn = g_stats[32 + tid] * (1.0f / (3.0f * N_NODES));
        prm[32 + tid] = bn_weight[16 + tid] * rsqrtf(fn + BN_EPS);
    }
    __syncthreads();

    int idx = blockIdx.x * 256 + tid;  // grid covers exactly N_NODES*64
    int f = idx & 63;
    float o = g_out[idx];
    if (f < 16)
        out[idx] = (o - prm[f]) * prm[16 + f] + bn_bias[f];
    else
        out[idx] = o * prm[32 + (f - 16) / 3];
}

// ---------------- launch ----------------
extern "C" void kernel_launch(void* const* d_in, const int* in_sizes, int n_in,
                              void* d_out, int out_size) {
    const float* node_attr = (const float*)d_in[0];
    const float* edge_attr = (const float*)d_in[1];
    const float* edge_sh = (const float*)d_in[2];
    const float* w1 = (const float*)d_in[3];
    const float* b1 = (const float*)d_in[4];
    const float* w2 = (const float*)d_in[5];
    const float* b2 = (const float*)d_in[6];
    const float* bnw = (const float*)d_in[7];
    const float* bnb = (const float*)d_in[8];
    const int* eidx = (const int*)d_in[9];
    float* out = (float*)d_out;

    cudaFuncSetAttribute(k_tp, cudaFuncAttributeMaxDynamicSharedMemorySize, SMEM_TP);

    k_prep<<<128, 256>>>(w2, w1);
    k_tp<<<(N_EDGES + 127) / 128, 256, SMEM_TP>>>(node_attr, edge_sh, b2, eidx,
                                                  edge_attr, b1);
    k_stats<<<N_NODES / 16, 256>>>(node_attr);
    k_norm<<<(N_NODES * 64) / 256, 256>>>(bnw, bnb, out);
}

// round 15
// speedup vs baseline: 1.1586x; 1.0298x over previous
#include <cuda_runtime.h>
#include <cuda_bf16.h>

#define N_NODES 50000
#define N_EDGES 200000
#define MUL 16
#define ALPHA 0.17677669529663687f
#define INV_SQRT3 0.5773502691896258f
#define AIS (ALPHA * INV_SQRT3)
#define BN_EPS 1e-5f

typedef unsigned long long ull;
typedef unsigned int u32;

// ---------------- mma / ldmatrix / cp.async (baseline PTX, no 'a' gates) ----------------
__device__ __forceinline__ u32 smem_u32(const void* p) {
    u32 a;
    asm("{ .reg .u64 t; cvta.to.shared.u64 t, %1; cvt.u32.u64 %0, t; }" : "=r"(a) : "l"(p));
    return a;
}
__device__ __forceinline__ void ldsm4(u32& r0, u32& r1, u32& r2, u32& r3, u32 addr) {
    asm volatile("ldmatrix.sync.aligned.m8n8.x4.shared.b16 {%0,%1,%2,%3}, [%4];"
                 : "=r"(r0), "=r"(r1), "=r"(r2), "=r"(r3) : "r"(addr));
}
__device__ __forceinline__ void mma16816(float* d, const u32* a, u32 b0, u32 b1) {
    asm volatile(
        "mma.sync.aligned.m16n8k16.row.col.f32.bf16.bf16.f32 "
        "{%0,%1,%2,%3}, {%4,%5,%6,%7}, {%8,%9}, {%0,%1,%2,%3};"
        : "+f"(d[0]), "+f"(d[1]), "+f"(d[2]), "+f"(d[3])
        : "r"(a[0]), "r"(a[1]), "r"(a[2]), "r"(a[3]), "r"(b0), "r"(b1));
}
__device__ __forceinline__ void cpasync16(u32 dst, const void* src) {
    asm volatile("cp.async.ca.shared.global [%0], [%1], 16;" :: "r"(dst), "l"(src) : "memory");
}
#define CP_COMMIT() asm volatile("cp.async.commit_group;" ::: "memory")
#define CP_WAIT0() asm volatile("cp.async.wait_group 0;" ::: "memory")

// vectorized global f32 reduction (PTX 8.1+, sm_90+; 8B-aligned address required)
__device__ __forceinline__ void red2(float* p, float a, float b) {
    asm volatile("red.global.add.v2.f32 [%0], {%1, %2};" :: "l"(p), "f"(a), "f"(b) : "memory");
}

// pack two fp32 -> bf16x2 hi/lo split
__device__ __forceinline__ void split_pack(float va, float vb, u32& hi, u32& lo) {
    __nv_bfloat16 ha = __float2bfloat16(va), hb = __float2bfloat16(vb);
    float la = va - __bfloat162float(ha), lb = vb - __bfloat162float(hb);
    __nv_bfloat162 hp, lp;
    hp.x = ha; hp.y = hb;
    lp.x = __float2bfloat16(la); lp.y = __float2bfloat16(lb);
    hi = *(u32*)&hp;
    lo = *(u32*)&lp;
}

// ---------------- scratch ----------------
__device__ __align__(16) __nv_bfloat16 g_BThi[1024 * 64];
__device__ __align__(16) __nv_bfloat16 g_BTlo[1024 * 64];
__device__ __align__(16) __nv_bfloat16 g_W1Thi[64 * 64];
__device__ __align__(16) __nv_bfloat16 g_W1Tlo[64 * 64];
__device__ __align__(256) float g_agg[N_NODES * 64];  // zero on first run (BSS); restored by k_stats
__device__ float g_cnt[N_NODES];                      // same invariant
__device__ float g_out[N_NODES * 64];
__device__ float g_stats[48];

// ---------------- kernel 0: prep (zero g_stats + split w2^T and w1^T) ----------------
__global__ void k_prep(const float* __restrict__ w2, const float* __restrict__ w1) {
    int idx = blockIdx.x * blockDim.x + threadIdx.x;
    int stride = gridDim.x * blockDim.x;
    if (idx < 48) g_stats[idx] = 0.0f;

    // w2 split: g_BT[c][j] = split(w2[j][c])
    for (int i = idx; i < 65536; i += stride) {
        int j = i >> 10, c = i & 1023;
        float v = w2[i];
        __nv_bfloat16 hi = __float2bfloat16(v);
        g_BThi[c * 64 + j] = hi;
        g_BTlo[c * 64 + j] = __float2bfloat16(v - __bfloat162float(hi));
    }
    // w1 split: g_W1T[c][f] = split(w1[f][c])
    if (idx < 4096) {
        int f = idx >> 6, c = idx & 63;
        float v = w1[idx];
        __nv_bfloat16 hi = __float2bfloat16(v);
        g_W1Thi[c * 64 + f] = hi;
        g_W1Tlo[c * 64 + f] = __float2bfloat16(v - __bfloat162float(hi));
    }
}

// ---------------- kernel 1: fused GEMM1 + GEMM2 + TP + scatter ----------------
// 256 threads, 128 edges/block, 2 blocks/SM, warp owns 16 edges.
// Main loop: bq processed in PAIRS (4 independent HMMA accumulation chains).
#define OFF_AB 0            // 36864: w1T staging (18432), then B dbl buf (2 x 18432)
#define OFF_CA 36864
#define OFF_CB 45312
#define OFF_CX 53760
#define OFF_CD 62208
#define OFF_B2 87552
#define OFF_SHS 91648
#define SMEM_TP 93696

__global__ __launch_bounds__(256, 2) void k_tp(const float* __restrict__ node_attr,
                                               const float* __restrict__ edge_sh,
                                               const float* __restrict__ b2,
                                               const int* __restrict__ edge_index,
                                               const float* __restrict__ ea,
                                               const float* __restrict__ b1g) {
    extern __shared__ __align__(16) char smem[];
    float* cA = (float*)(smem + OFF_CA);
    float* cB = (float*)(smem + OFF_CB);
    float* cX = (float*)(smem + OFF_CX);
    float* cD = (float*)(smem + OFF_CD);
    float* b2s = (float*)(smem + OFF_B2);
    float* shs = (float*)(smem + OFF_SHS);
    __shared__ int srcs[128], dsts[128];

    int tid = threadIdx.x;
    int lane = tid & 31;
    int wid = tid >> 5;
    int e0 = blockIdx.x * 128;
    u32 sbase = smem_u32(smem);

    if (tid < 128) {
        int e = e0 + tid;
        bool val = e < N_EDGES;
        float4 sh = val ? ((const float4*)edge_sh)[e] : make_float4(0, 0, 0, 0);
        *(float4*)&shs[tid * 4] = sh;
        srcs[tid] = val ? edge_index[e] : 0;
        dsts[tid] = val ? edge_index[N_EDGES + e] : -1;
    }
    for (int idx = tid; idx < 1024; idx += 256) b2s[idx] = b2[idx];
    __syncthreads();

    // stage w1T hi/lo into OFF_AB (rows padded to 144B), via cp.async
#pragma unroll 1
    for (int idx = tid; idx < 1024; idx += 256) {
        int half = idx >> 9, rem = idx & 511;
        int rr = rem >> 3, qq = rem & 7;
        const char* srcb = (const char*)(half ? g_W1Tlo : g_W1Thi);
        cpasync16(sbase + OFF_AB + half * 9216 + rr * 144 + qq * 16,
                  srcb + rr * 128 + qq * 16);
    }
    CP_COMMIT();

    // coefficients [i][132e] (overlaps w1T copy)
    for (int idx = tid; idx < 2048; idx += 256) {
        int e = idx >> 4, i = idx & 15;
        int d = dsts[e];
        float ss = shs[e * 4], s1 = shs[e * 4 + 1], s2 = shs[e * 4 + 2], s3 = shs[e * 4 + 3];
        float xs = 0, x0 = 0, x1 = 0, x2 = 0;
        if (d >= 0) {
            xs = node_attr[d * 64 + i];
            const float* xp = &node_attr[d * 64 + 16 + 3 * i];
            x0 = xp[0]; x1 = xp[1]; x2 = xp[2];
        }
        cA[i * 132 + e] = ALPHA * ss * xs;
        cX[i * 132 + e] = AIS * xs;
        cB[i * 132 + e] = AIS * (x0 * s1 + x1 * s2 + x2 * s3);
        cD[(0 * 16 + i) * 132 + e] = AIS * ss * x0;
        cD[(1 * 16 + i) * 132 + e] = AIS * ss * x1;
        cD[(2 * 16 + i) * 132 + e] = AIS * ss * x2;
    }
    CP_WAIT0();
    __syncthreads();  // w1T staged; coefficients visible

    int q = lane & 3;
    int r = lane >> 2;
    int el0 = wid * 16 + r;
    u32 laneB = (u32)(((lane & 7) + ((lane >> 4) & 1) * 8) * 144 + ((lane >> 3) & 1) * 16);

    // ---- GEMM1: h = relu(ea @ w1 + b1), D-frags -> gemm2 A-frags ----
    u32 aH[4][4], aL[4][4];
    {
        float D1[4][8];
#pragma unroll
        for (int bq = 0; bq < 4; bq++)
#pragma unroll
            for (int z = 0; z < 8; z++) D1[bq][z] = 0.0f;

        bool v0 = (e0 + el0) < N_EDGES;
        bool v1 = (e0 + el0 + 8) < N_EDGES;
        const float* row0 = ea + (e0 + el0) * 64;
        const float* row1 = ea + (e0 + el0 + 8) * 64;
        float2 z2 = make_float2(0, 0);

#pragma unroll
        for (int ksin = 0; ksin < 4; ksin++) {
            int c = ksin * 16 + 2 * q;
            float2 x00 = v0 ? *(const float2*)&row0[c] : z2;
            float2 x10 = v1 ? *(const float2*)&row1[c] : z2;
            float2 x01 = v0 ? *(const float2*)&row0[c + 8] : z2;
            float2 x11 = v1 ? *(const float2*)&row1[c + 8] : z2;
            u32 eH[4], eL[4];
            split_pack(x00.x, x00.y, eH[0], eL[0]);
            split_pack(x10.x, x10.y, eH[1], eL[1]);
            split_pack(x01.x, x01.y, eH[2], eL[2]);
            split_pack(x11.x, x11.y, eH[3], eL[3]);

#pragma unroll
            for (int bq = 0; bq < 4; bq++) {
                u32 bh0, bh1, bh2, bh3, bl0, bl1, bl2, bl3;
                u32 ad = sbase + OFF_AB + laneB + bq * 2304 + ksin * 32;
                ldsm4(bh0, bh1, bh2, bh3, ad);
                ldsm4(bl0, bl1, bl2, bl3, ad + 9216);
                mma16816(&D1[bq][0], eH, bh0, bh1);
                mma16816(&D1[bq][4], eH, bh2, bh3);
                mma16816(&D1[bq][0], eH, bl0, bl1);
                mma16816(&D1[bq][4], eH, bl2, bl3);
                mma16816(&D1[bq][0], eL, bh0, bh1);
                mma16816(&D1[bq][4], eL, bh2, bh3);
            }
        }

        // bias + relu + hi/lo split: D1[ks] group (n-cols ks*16..+15) == gemm2 k-group ks
#pragma unroll
        for (int ks = 0; ks < 4; ks++) {
            int cb = ks * 16 + 2 * q;
            float2 b01 = *(const float2*)&b1g[cb];
            float2 b89 = *(const float2*)&b1g[cb + 8];
            float d0 = fmaxf(D1[ks][0] + b01.x, 0.0f);
            float d1 = fmaxf(D1[ks][1] + b01.y, 0.0f);
            float d2 = fmaxf(D1[ks][2] + b01.x, 0.0f);
            float d3 = fmaxf(D1[ks][3] + b01.y, 0.0f);
            float d4 = fmaxf(D1[ks][4] + b89.x, 0.0f);
            float d5 = fmaxf(D1[ks][5] + b89.y, 0.0f);
            float d6 = fmaxf(D1[ks][6] + b89.x, 0.0f);
            float d7 = fmaxf(D1[ks][7] + b89.y, 0.0f);
            split_pack(d0, d1, aH[ks][0], aL[ks][0]);
            split_pack(d2, d3, aH[ks][1], aL[ks][1]);
            split_pack(d4, d5, aH[ks][2], aL[ks][2]);
            split_pack(d6, d7, aH[ks][3], aL[ks][3]);
        }
    }
    __syncthreads();  // all warps done reading w1T before B overwrites

    // issue B slice 0 into buffer 0
#pragma unroll 1
    for (int idx = tid; idx < 1024; idx += 256) {
        int half = idx >> 9, rem = idx & 511;
        int rr = rem >> 3, qq = rem & 7;
        const char* srcb = (const char*)(half ? g_BTlo : g_BThi);
        cpasync16(sbase + OFF_AB + half * 9216 + rr * 144 + qq * 16,
                  srcb + rr * 128 + qq * 16);
    }
    CP_COMMIT();

    float accS[2][4], accR[2][4], accV[2][4][3];
#pragma unroll
    for (int m = 0; m < 2; m++)
#pragma unroll
        for (int s = 0; s < 4; s++) {
            accS[m][s] = 0; accR[m][s] = 0;
            accV[m][s][0] = 0; accV[m][s][1] = 0; accV[m][s][2] = 0;
        }

#pragma unroll 1
    for (int sl = 0; sl < 16; sl++) {
        int t = sl >> 2, g = sl & 3;
        int buf = sl & 1;
        CP_WAIT0();
        __syncthreads();  // slice sl ready; compute(sl-1) fully done
        if (sl < 15) {
            int nb = (sl + 1) & 1;
            const char* bhp = (const char*)&g_BThi[(sl + 1) * 64 * 64];
            const char* blp = (const char*)&g_BTlo[(sl + 1) * 64 * 64];
#pragma unroll 1
            for (int idx = tid; idx < 1024; idx += 256) {
                int half = idx >> 9, rem = idx & 511;
                int rr = rem >> 3, qq = rem & 7;
                cpasync16(sbase + OFF_AB + nb * 18432 + half * 9216 + rr * 144 + qq * 16,
                          (half ? blp : bhp) + rr * 128 + qq * 16);
            }
            CP_COMMIT();
        }

        u32 bHbase = sbase + OFF_AB + buf * 18432 + laneB;
        u32 bLbase = bHbase + 9216;

        // bq pairs: 4 independent accumulation chains (d[0][0:4], d[0][4:8], d[1][...])
#pragma unroll
        for (int bqp = 0; bqp < 2; bqp++) {
            float d[2][8];
#pragma unroll
            for (int u = 0; u < 2; u++)
#pragma unroll
                for (int z = 0; z < 8; z++) d[u][z] = 0.0f;

#pragma unroll
            for (int ks = 0; ks < 4; ks++) {
                u32 bh[2][4], bl[2][4];
#pragma unroll
                for (int u = 0; u < 2; u++) {
                    int bq = bqp * 2 + u;
                    ldsm4(bl[u][0], bl[u][1], bl[u][2], bl[u][3],
                          bLbase + bq * 2304 + ks * 32);
                    ldsm4(bh[u][0], bh[u][1], bh[u][2], bh[u][3],
                          bHbase + bq * 2304 + ks * 32);
                }
                // aH x bl first (bl registers die early), interleaved across u
#pragma unroll
                for (int u = 0; u < 2; u++) {
                    mma16816(&d[u][0], aH[ks], bl[u][0], bl[u][1]);
                    mma16816(&d[u][4], aH[ks], bl[u][2], bl[u][3]);
                }
#pragma unroll
                for (int u = 0; u < 2; u++) {
                    mma16816(&d[u][0], aH[ks], bh[u][0], bh[u][1]);
                    mma16816(&d[u][4], aH[ks], bh[u][2], bh[u][3]);
                }
#pragma unroll
                for (int u = 0; u < 2; u++) {
                    mma16816(&d[u][0], aL[ks], bh[u][0], bh[u][1]);
                    mma16816(&d[u][4], aL[ks], bh[u][2], bh[u][3]);
                }
            }

            // epilogue for both bq of the pair
#pragma unroll
            for (int u = 0; u < 2; u++) {
                int bq = bqp * 2 + u;
                int i = g * 4 + bq;
                int colb = g * 64 + bq * 16 + 2 * q;
                if (t < 3) {
                    const float* cp = (t == 0) ? cA : (t == 1) ? cB : cX;
                    float cv0 = cp[i * 132 + el0];
                    float cv1 = cp[i * 132 + el0 + 8];
                    float (*acc)[4] = (t == 2) ? accR : accS;
#pragma unroll
                    for (int f = 0; f < 2; f++) {
                        float bb0 = b2s[t * 256 + colb + f * 8];
                        float bb1 = b2s[t * 256 + colb + f * 8 + 1];
                        acc[0][f * 2 + 0] += cv0 * (d[u][f * 4 + 0] + bb0);
                        acc[0][f * 2 + 1] += cv0 * (d[u][f * 4 + 1] + bb1);
                        acc[1][f * 2 + 0] += cv1 * (d[u][f * 4 + 2] + bb0);
                        acc[1][f * 2 + 1] += cv1 * (d[u][f * 4 + 3] + bb1);
                    }
                } else {
                    float cd0[3], cd1[3];
#pragma unroll
                    for (int mm = 0; mm < 3; mm++) {
                        cd0[mm] = cD[(mm * 16 + i) * 132 + el0];
                        cd1[mm] = cD[(mm * 16 + i) * 132 + el0 + 8];
                    }
#pragma unroll
                    for (int f = 0; f < 2; f++) {
                        float bb0 = b2s[768 + colb + f * 8];
                        float bb1 = b2s[768 + colb + f * 8 + 1];
                        float w00 = d[u][f * 4 + 0] + bb0, w01 = d[u][f * 4 + 1] + bb1;
                        float w10 = d[u][f * 4 + 2] + bb0, w11 = d[u][f * 4 + 3] + bb1;
#pragma unroll
                        for (int mm = 0; mm < 3; mm++) {
                            accV[0][f * 2 + 0][mm] += cd0[mm] * w00;
                            accV[0][f * 2 + 1][mm] += cd0[mm] * w01;
                            accV[1][f * 2 + 0][mm] += cd1[mm] * w10;
                            accV[1][f * 2 + 1][mm] += cd1[mm] * w11;
                        }
                    }
                }
            }
        }
    }

    // scatter: vectorized red.v2.f32
#pragma unroll
    for (int m = 0; m < 2; m++) {
        int el = el0 + 8 * m;
        if (e0 + el < N_EDGES) {
            int src = srcs[el];
            float s1 = shs[el * 4 + 1], s2 = shs[el * 4 + 2], s3 = shs[el * 4 + 3];
            float* base = &g_agg[src * 64];
            red2(base + 2 * q, accS[m][0], accS[m][1]);
            red2(base + 2 * q + 8, accS[m][2], accS[m][3]);
#pragma unroll
            for (int p = 0; p < 2; p++) {
                float r0 = accR[m][2 * p], r1 = accR[m][2 * p + 1];
                float v0 = accV[m][2 * p][0] + s1 * r0;
                float v1 = accV[m][2 * p][1] + s2 * r0;
                float v2 = accV[m][2 * p][2] + s3 * r0;
                float v3 = accV[m][2 * p + 1][0] + s1 * r1;
                float v4 = accV[m][2 * p + 1][1] + s2 * r1;
                float v5 = accV[m][2 * p + 1][2] + s3 * r1;
                float* vp = base + 16 + 6 * q + 24 * p;
                red2(vp, v0, v1);
                red2(vp + 2, v2, v3);
                red2(vp + 4, v4, v5);
            }
            if (q == 0) atomicAdd(&g_cnt[src], 1.0f);
        }
    }
}

// ---------------- kernel 2: mean + residual + BN stats (+invariant restore) ----------------
__global__ __launch_bounds__(256) void k_stats(const float* __restrict__ node_attr) {
    __shared__ float sstat[48];
    int tid = threadIdx.x;
    if (tid < 48) sstat[tid] = 0.0f;
    __syncthreads();

    int n = blockIdx.x * 16 + (tid >> 4);  // grid covers exactly N_NODES
    int q = tid & 15;
    float cnt = g_cnt[n];
    float inv = 1.0f / fmaxf(cnt, 1.0f);
    float4 ag = *(const float4*)&g_agg[n * 64 + q * 4];
    // restore zero-invariant: each thread zeroes the exclusive 16B it consumed;
    // g_cnt word shared by 16 threads -> one writer after syncwarp
    *(float4*)&g_agg[n * 64 + q * 4] = make_float4(0, 0, 0, 0);
    __syncwarp();
    if (q == 0) g_cnt[n] = 0.0f;

    float4 na = *(const float4*)&node_attr[n * 64 + q * 4];
    float o[4] = {fmaf(ag.x, inv, na.x), fmaf(ag.y, inv, na.y),
                  fmaf(ag.z, inv, na.z), fmaf(ag.w, inv, na.w)};
    *(float4*)&g_out[n * 64 + q * 4] = make_float4(o[0], o[1], o[2], o[3]);
    if (q < 4) {
#pragma unroll
        for (int t = 0; t < 4; t++) {
            atomicAdd(&sstat[q * 4 + t], o[t]);
            atomicAdd(&sstat[16 + q * 4 + t], o[t] * o[t]);
        }
    } else {
#pragma unroll
        for (int t = 0; t < 4; t++) {
            int k = (q * 4 + t - 16) / 3;
            atomicAdd(&sstat[32 + k], o[t] * o[t]);
        }
    }
    __syncthreads();
    if (tid < 48) atomicAdd(&g_stats[tid], sstat[tid]);
}

// ---------------- kernel 3: normalize (BN finalize folded in) ----------------
__global__ __launch_bounds__(256) void k_norm(const float* __restrict__ bn_weight,
                                              const float* __restrict__ bn_bias,
                                              float* __restrict__ out) {
    __shared__ float prm[48];
    int tid = threadIdx.x;
    if (tid < 16) {
        float mean = g_stats[tid] * (1.0f / N_NODES);
        float var = g_stats[16 + tid] * (1.0f / N_NODES) - mean * mean;
        prm[tid] = mean;
        prm[16 + tid] = bn_weight[tid] * rsqrtf(var + BN_EPS);
        float fn = g_stats[32 + tid] * (1.0f / (3.0f * N_NODES));
        prm[32 + tid] = bn_weight[16 + tid] * rsqrtf(fn + BN_EPS);
    }
    __syncthreads();

    int idx = blockIdx.x * 256 + tid;  // grid covers exactly N_NODES*64
    int f = idx & 63;
    float o = g_out[idx];
    if (f < 16)
        out[idx] = (o - prm[f]) * prm[16 + f] + bn_bias[f];
    else
        out[idx] = o * prm[32 + (f - 16) / 3];
}

// ---------------- launch ----------------
extern "C" void kernel_launch(void* const* d_in, const int* in_sizes, int n_in,
                              void* d_out, int out_size) {
    const float* node_attr = (const float*)d_in[0];
    const float* edge_attr = (const float*)d_in[1];
    const float* edge_sh = (const float*)d_in[2];
    const float* w1 = (const float*)d_in[3];
    const float* b1 = (const float*)d_in[4];
    const float* w2 = (const float*)d_in[5];
    const float* b2 = (const float*)d_in[6];
    const float* bnw = (const float*)d_in[7];
    const float* bnb = (const float*)d_in[8];
    const int* eidx = (const int*)d_in[9];
    float* out = (float*)d_out;

    cudaFuncSetAttribute(k_tp, cudaFuncAttributeMaxDynamicSharedMemorySize, SMEM_TP);

    k_prep<<<128, 256>>>(w2, w1);
    k_tp<<<(N_EDGES + 127) / 128, 256, SMEM_TP>>>(node_attr, edge_sh, b2, eidx,
                                                  edge_attr, b1);
    k_stats<<<N_NODES / 16, 256>>>(node_attr);
    k_norm<<<(N_NODES * 64) / 256, 256>>>(bnw, bnb, out);
}

// round 16
// speedup vs baseline: 1.1646x; 1.0052x over previous
#include <cuda_runtime.h>
#include <cuda_bf16.h>

#define N_NODES 50000
#define N_EDGES 200000
#define MUL 16
#define ALPHA 0.17677669529663687f
#define INV_SQRT3 0.5773502691896258f
#define AIS (ALPHA * INV_SQRT3)
#define BN_EPS 1e-5f

typedef unsigned long long ull;
typedef unsigned int u32;

// ---------------- mma / ldmatrix / cp.async (baseline PTX, no 'a' gates) ----------------
__device__ __forceinline__ u32 smem_u32(const void* p) {
    u32 a;
    asm("{ .reg .u64 t; cvta.to.shared.u64 t, %1; cvt.u32.u64 %0, t; }" : "=r"(a) : "l"(p));
    return a;
}
__device__ __forceinline__ void ldsm4(u32& r0, u32& r1, u32& r2, u32& r3, u32 addr) {
    asm volatile("ldmatrix.sync.aligned.m8n8.x4.shared.b16 {%0,%1,%2,%3}, [%4];"
                 : "=r"(r0), "=r"(r1), "=r"(r2), "=r"(r3) : "r"(addr));
}
__device__ __forceinline__ void mma16816(float* d, const u32* a, u32 b0, u32 b1) {
    asm volatile(
        "mma.sync.aligned.m16n8k16.row.col.f32.bf16.bf16.f32 "
        "{%0,%1,%2,%3}, {%4,%5,%6,%7}, {%8,%9}, {%0,%1,%2,%3};"
        : "+f"(d[0]), "+f"(d[1]), "+f"(d[2]), "+f"(d[3])
        : "r"(a[0]), "r"(a[1]), "r"(a[2]), "r"(a[3]), "r"(b0), "r"(b1));
}
__device__ __forceinline__ void cpasync16(u32 dst, const void* src) {
    asm volatile("cp.async.ca.shared.global [%0], [%1], 16;" :: "r"(dst), "l"(src) : "memory");
}
#define CP_COMMIT() asm volatile("cp.async.commit_group;" ::: "memory")
#define CP_WAIT0() asm volatile("cp.async.wait_group 0;" ::: "memory")
#define CP_WAIT1() asm volatile("cp.async.wait_group 1;" ::: "memory")

// vectorized global f32 reduction (PTX 8.1+, sm_90+; 8B-aligned address required)
__device__ __forceinline__ void red2(float* p, float a, float b) {
    asm volatile("red.global.add.v2.f32 [%0], {%1, %2};" :: "l"(p), "f"(a), "f"(b) : "memory");
}

// pack two fp32 -> bf16x2 hi/lo split
__device__ __forceinline__ void split_pack(float va, float vb, u32& hi, u32& lo) {
    __nv_bfloat16 ha = __float2bfloat16(va), hb = __float2bfloat16(vb);
    float la = va - __bfloat162float(ha), lb = vb - __bfloat162float(hb);
    __nv_bfloat162 hp, lp;
    hp.x = ha; hp.y = hb;
    lp.x = __float2bfloat16(la); lp.y = __float2bfloat16(lb);
    hi = *(u32*)&hp;
    lo = *(u32*)&lp;
}

// ---------------- scratch ----------------
__device__ __align__(16) __nv_bfloat16 g_BThi[1024 * 64];
__device__ __align__(16) __nv_bfloat16 g_BTlo[1024 * 64];
__device__ __align__(16) __nv_bfloat16 g_W1Thi[64 * 64];
__device__ __align__(16) __nv_bfloat16 g_W1Tlo[64 * 64];
__device__ __align__(256) float g_agg[N_NODES * 64];  // zero on first run (BSS); restored by k_stats
__device__ float g_cnt[N_NODES];                      // same invariant
__device__ float g_out[N_NODES * 64];
__device__ float g_stats[48];

// ---------------- kernel 0: prep (zero g_stats + split w2^T and w1^T) ----------------
__global__ void k_prep(const float* __restrict__ w2, const float* __restrict__ w1) {
    int idx = blockIdx.x * blockDim.x + threadIdx.x;
    int stride = gridDim.x * blockDim.x;
    if (idx < 48) g_stats[idx] = 0.0f;

    // w2 split: g_BT[c][j] = split(w2[j][c])
    for (int i = idx; i < 65536; i += stride) {
        int j = i >> 10, c = i & 1023;
        float v = w2[i];
        __nv_bfloat16 hi = __float2bfloat16(v);
        g_BThi[c * 64 + j] = hi;
        g_BTlo[c * 64 + j] = __float2bfloat16(v - __bfloat162float(hi));
    }
    // w1 split: g_W1T[c][f] = split(w1[f][c])
    if (idx < 4096) {
        int f = idx >> 6, c = idx & 63;
        float v = w1[idx];
        __nv_bfloat16 hi = __float2bfloat16(v);
        g_W1Thi[c * 64 + f] = hi;
        g_W1Tlo[c * 64 + f] = __float2bfloat16(v - __bfloat162float(hi));
    }
}

// ---------------- kernel 1: fused GEMM1 + GEMM2 + TP + scatter ----------------
// 256 threads, 128 edges/block, 2 blocks/SM, warp owns 16 edges.
// B ring: 3 x 18432B (144B-padded rows); copies lead compute by 2 slices
// (wait_group 1 at steady state). bq pairs: 4 independent HMMA chains.
#define OFF_AB 0            // 3 x 18432 ring; buf 0 holds w1T during prologue
#define OFF_CA 55296
#define OFF_CB 63744
#define OFF_CX 72192
#define OFF_CD 80640
#define OFF_B2 105984
#define OFF_SHS 110080
#define SMEM_TP 112128

__global__ __launch_bounds__(256, 2) void k_tp(const float* __restrict__ node_attr,
                                               const float* __restrict__ edge_sh,
                                               const float* __restrict__ b2,
                                               const int* __restrict__ edge_index,
                                               const float* __restrict__ ea,
                                               const float* __restrict__ b1g) {
    extern __shared__ __align__(16) char smem[];
    float* cA = (float*)(smem + OFF_CA);
    float* cB = (float*)(smem + OFF_CB);
    float* cX = (float*)(smem + OFF_CX);
    float* cD = (float*)(smem + OFF_CD);
    float* b2s = (float*)(smem + OFF_B2);
    float* shs = (float*)(smem + OFF_SHS);
    __shared__ int srcs[128], dsts[128];

    int tid = threadIdx.x;
    int lane = tid & 31;
    int wid = tid >> 5;
    int e0 = blockIdx.x * 128;
    u32 sbase = smem_u32(smem);

    if (tid < 128) {
        int e = e0 + tid;
        bool val = e < N_EDGES;
        float4 sh = val ? ((const float4*)edge_sh)[e] : make_float4(0, 0, 0, 0);
        *(float4*)&shs[tid * 4] = sh;
        srcs[tid] = val ? edge_index[e] : 0;
        dsts[tid] = val ? edge_index[N_EDGES + e] : -1;
    }
    for (int idx = tid; idx < 1024; idx += 256) b2s[idx] = b2[idx];
    __syncthreads();

    // stage w1T hi/lo into ring buf 0 (rows padded to 144B), via cp.async
#pragma unroll 1
    for (int idx = tid; idx < 1024; idx += 256) {
        int half = idx >> 9, rem = idx & 511;
        int rr = rem >> 3, qq = rem & 7;
        const char* srcb = (const char*)(half ? g_W1Tlo : g_W1Thi);
        cpasync16(sbase + OFF_AB + half * 9216 + rr * 144 + qq * 16,
                  srcb + rr * 128 + qq * 16);
    }
    CP_COMMIT();

    // coefficients [i][132e] (overlaps w1T copy)
    for (int idx = tid; idx < 2048; idx += 256) {
        int e = idx >> 4, i = idx & 15;
        int d = dsts[e];
        float ss = shs[e * 4], s1 = shs[e * 4 + 1], s2 = shs[e * 4 + 2], s3 = shs[e * 4 + 3];
        float xs = 0, x0 = 0, x1 = 0, x2 = 0;
        if (d >= 0) {
            xs = node_attr[d * 64 + i];
            const float* xp = &node_attr[d * 64 + 16 + 3 * i];
            x0 = xp[0]; x1 = xp[1]; x2 = xp[2];
        }
        cA[i * 132 + e] = ALPHA * ss * xs;
        cX[i * 132 + e] = AIS * xs;
        cB[i * 132 + e] = AIS * (x0 * s1 + x1 * s2 + x2 * s3);
        cD[(0 * 16 + i) * 132 + e] = AIS * ss * x0;
        cD[(1 * 16 + i) * 132 + e] = AIS * ss * x1;
        cD[(2 * 16 + i) * 132 + e] = AIS * ss * x2;
    }
    CP_WAIT0();
    __syncthreads();  // w1T staged; coefficients visible

    int q = lane & 3;
    int r = lane >> 2;
    int el0 = wid * 16 + r;
    u32 laneB = (u32)(((lane & 7) + ((lane >> 4) & 1) * 8) * 144 + ((lane >> 3) & 1) * 16);

    // ---- GEMM1: h = relu(ea @ w1 + b1), D-frags -> gemm2 A-frags ----
    u32 aH[4][4], aL[4][4];
    {
        float D1[4][8];
#pragma unroll
        for (int bq = 0; bq < 4; bq++)
#pragma unroll
            for (int z = 0; z < 8; z++) D1[bq][z] = 0.0f;

        bool v0 = (e0 + el0) < N_EDGES;
        bool v1 = (e0 + el0 + 8) < N_EDGES;
        const float* row0 = ea + (e0 + el0) * 64;
        const float* row1 = ea + (e0 + el0 + 8) * 64;
        float2 z2 = make_float2(0, 0);

#pragma unroll
        for (int ksin = 0; ksin < 4; ksin++) {
            int c = ksin * 16 + 2 * q;
            float2 x00 = v0 ? *(const float2*)&row0[c] : z2;
            float2 x10 = v1 ? *(const float2*)&row1[c] : z2;
            float2 x01 = v0 ? *(const float2*)&row0[c + 8] : z2;
            float2 x11 = v1 ? *(const float2*)&row1[c + 8] : z2;
            u32 eH[4], eL[4];
            split_pack(x00.x, x00.y, eH[0], eL[0]);
            split_pack(x10.x, x10.y, eH[1], eL[1]);
            split_pack(x01.x, x01.y, eH[2], eL[2]);
            split_pack(x11.x, x11.y, eH[3], eL[3]);

#pragma unroll
            for (int bq = 0; bq < 4; bq++) {
                u32 bh0, bh1, bh2, bh3, bl0, bl1, bl2, bl3;
                u32 ad = sbase + OFF_AB + laneB + bq * 2304 + ksin * 32;
                ldsm4(bh0, bh1, bh2, bh3, ad);
                ldsm4(bl0, bl1, bl2, bl3, ad + 9216);
                mma16816(&D1[bq][0], eH, bh0, bh1);
                mma16816(&D1[bq][4], eH, bh2, bh3);
                mma16816(&D1[bq][0], eH, bl0, bl1);
                mma16816(&D1[bq][4], eH, bl2, bl3);
                mma16816(&D1[bq][0], eL, bh0, bh1);
                mma16816(&D1[bq][4], eL, bh2, bh3);
            }
        }

        // bias + relu + hi/lo split: D1[ks] group (n-cols ks*16..+15) == gemm2 k-group ks
#pragma unroll
        for (int ks = 0; ks < 4; ks++) {
            int cb = ks * 16 + 2 * q;
            float2 b01 = *(const float2*)&b1g[cb];
            float2 b89 = *(const float2*)&b1g[cb + 8];
            float d0 = fmaxf(D1[ks][0] + b01.x, 0.0f);
            float d1 = fmaxf(D1[ks][1] + b01.y, 0.0f);
            float d2 = fmaxf(D1[ks][2] + b01.x, 0.0f);
            float d3 = fmaxf(D1[ks][3] + b01.y, 0.0f);
            float d4 = fmaxf(D1[ks][4] + b89.x, 0.0f);
            float d5 = fmaxf(D1[ks][5] + b89.y, 0.0f);
            float d6 = fmaxf(D1[ks][6] + b89.x, 0.0f);
            float d7 = fmaxf(D1[ks][7] + b89.y, 0.0f);
            split_pack(d0, d1, aH[ks][0], aL[ks][0]);
            split_pack(d2, d3, aH[ks][1], aL[ks][1]);
            split_pack(d4, d5, aH[ks][2], aL[ks][2]);
            split_pack(d6, d7, aH[ks][3], aL[ks][3]);
        }
    }
    __syncthreads();  // all warps done reading w1T (buf 0) before B overwrites

    // prologue: issue B slices 0 -> buf 0, 1 -> buf 1 (two commit groups)
#pragma unroll
    for (int ns = 0; ns < 2; ns++) {
        const char* bhp = (const char*)&g_BThi[ns * 64 * 64];
        const char* blp = (const char*)&g_BTlo[ns * 64 * 64];
        u32 dbase = sbase + OFF_AB + ns * 18432;
#pragma unroll 1
        for (int idx = tid; idx < 1024; idx += 256) {
            int half = idx >> 9, rem = idx & 511;
            int rr = rem >> 3, qq = rem & 7;
            cpasync16(dbase + half * 9216 + rr * 144 + qq * 16,
                      (half ? blp : bhp) + rr * 128 + qq * 16);
        }
        CP_COMMIT();
    }

    float accS[2][4], accR[2][4], accV[2][4][3];
#pragma unroll
    for (int m = 0; m < 2; m++)
#pragma unroll
        for (int s = 0; s < 4; s++) {
            accS[m][s] = 0; accR[m][s] = 0;
            accV[m][s][0] = 0; accV[m][s][1] = 0; accV[m][s][2] = 0;
        }

#pragma unroll 1
    for (int sl = 0; sl < 16; sl++) {
        int t = sl >> 2, g = sl & 3;
        if (sl < 15) CP_WAIT1();   // slice sl landed; slice sl+1 may still fly
        else CP_WAIT0();
        __syncthreads();  // all warps done with slice sl-1 (its buffer gets rewritten now)
        if (sl < 14) {
            int ns = sl + 2;
            const char* bhp = (const char*)&g_BThi[ns * 64 * 64];
            const char* blp = (const char*)&g_BTlo[ns * 64 * 64];
            u32 dbase = sbase + OFF_AB + (ns % 3) * 18432;
#pragma unroll 1
            for (int idx = tid; idx < 1024; idx += 256) {
                int half = idx >> 9, rem = idx & 511;
                int rr = rem >> 3, qq = rem & 7;
                cpasync16(dbase + half * 9216 + rr * 144 + qq * 16,
                          (half ? blp : bhp) + rr * 128 + qq * 16);
            }
            CP_COMMIT();
        }

        u32 bHbase = sbase + OFF_AB + (sl % 3) * 18432 + laneB;
        u32 bLbase = bHbase + 9216;

        // bq pairs: 4 independent accumulation chains
#pragma unroll
        for (int bqp = 0; bqp < 2; bqp++) {
            float d[2][8];
#pragma unroll
            for (int u = 0; u < 2; u++)
#pragma unroll
                for (int z = 0; z < 8; z++) d[u][z] = 0.0f;

#pragma unroll
            for (int ks = 0; ks < 4; ks++) {
                u32 bh[2][4], bl[2][4];
#pragma unroll
                for (int u = 0; u < 2; u++) {
                    int bq = bqp * 2 + u;
                    ldsm4(bl[u][0], bl[u][1], bl[u][2], bl[u][3],
                          bLbase + bq * 2304 + ks * 32);
                    ldsm4(bh[u][0], bh[u][1], bh[u][2], bh[u][3],
                          bHbase + bq * 2304 + ks * 32);
                }
#pragma unroll
                for (int u = 0; u < 2; u++) {
                    mma16816(&d[u][0], aH[ks], bl[u][0], bl[u][1]);
                    mma16816(&d[u][4], aH[ks], bl[u][2], bl[u][3]);
                }
#pragma unroll
                for (int u = 0; u < 2; u++) {
                    mma16816(&d[u][0], aH[ks], bh[u][0], bh[u][1]);
                    mma16816(&d[u][4], aH[ks], bh[u][2], bh[u][3]);
                }
#pragma unroll
                for (int u = 0; u < 2; u++) {
                    mma16816(&d[u][0], aL[ks], bh[u][0], bh[u][1]);
                    mma16816(&d[u][4], aL[ks], bh[u][2], bh[u][3]);
                }
            }

            // epilogue for both bq of the pair
#pragma unroll
            for (int u = 0; u < 2; u++) {
                int bq = bqp * 2 + u;
                int i = g * 4 + bq;
                int colb = g * 64 + bq * 16 + 2 * q;
                if (t < 3) {
                    const float* cp = (t == 0) ? cA : (t == 1) ? cB : cX;
                    float cv0 = cp[i * 132 + el0];
                    float cv1 = cp[i * 132 + el0 + 8];
                    float (*acc)[4] = (t == 2) ? accR : accS;
#pragma unroll
                    for (int f = 0; f < 2; f++) {
                        float bb0 = b2s[t * 256 + colb + f * 8];
                        float bb1 = b2s[t * 256 + colb + f * 8 + 1];
                        acc[0][f * 2 + 0] += cv0 * (d[u][f * 4 + 0] + bb0);
                        acc[0][f * 2 + 1] += cv0 * (d[u][f * 4 + 1] + bb1);
                        acc[1][f * 2 + 0] += cv1 * (d[u][f * 4 + 2] + bb0);
                        acc[1][f * 2 + 1] += cv1 * (d[u][f * 4 + 3] + bb1);
                    }
                } else {
                    float cd0[3], cd1[3];
#pragma unroll
                    for (int mm = 0; mm < 3; mm++) {
                        cd0[mm] = cD[(mm * 16 + i) * 132 + el0];
                        cd1[mm] = cD[(mm * 16 + i) * 132 + el0 + 8];
                    }
#pragma unroll
                    for (int f = 0; f < 2; f++) {
                        float bb0 = b2s[768 + colb + f * 8];
                        float bb1 = b2s[768 + colb + f * 8 + 1];
                        float w00 = d[u][f * 4 + 0] + bb0, w01 = d[u][f * 4 + 1] + bb1;
                        float w10 = d[u][f * 4 + 2] + bb0, w11 = d[u][f * 4 + 3] + bb1;
#pragma unroll
                        for (int mm = 0; mm < 3; mm++) {
                            accV[0][f * 2 + 0][mm] += cd0[mm] * w00;
                            accV[0][f * 2 + 1][mm] += cd0[mm] * w01;
                            accV[1][f * 2 + 0][mm] += cd1[mm] * w10;
                            accV[1][f * 2 + 1][mm] += cd1[mm] * w11;
                        }
                    }
                }
            }
        }
    }

    // scatter: vectorized red.v2.f32
#pragma unroll
    for (int m = 0; m < 2; m++) {
        int el = el0 + 8 * m;
        if (e0 + el < N_EDGES) {
            int src = srcs[el];
            float s1 = shs[el * 4 + 1], s2 = shs[el * 4 + 2], s3 = shs[el * 4 + 3];
            float* base = &g_agg[src * 64];
            red2(base + 2 * q, accS[m][0], accS[m][1]);
            red2(base + 2 * q + 8, accS[m][2], accS[m][3]);
#pragma unroll
            for (int p = 0; p < 2; p++) {
                float r0 = accR[m][2 * p], r1 = accR[m][2 * p + 1];
                float v0 = accV[m][2 * p][0] + s1 * r0;
                float v1 = accV[m][2 * p][1] + s2 * r0;
                float v2 = accV[m][2 * p][2] + s3 * r0;
                float v3 = accV[m][2 * p + 1][0] + s1 * r1;
                float v4 = accV[m][2 * p + 1][1] + s2 * r1;
                float v5 = accV[m][2 * p + 1][2] + s3 * r1;
                float* vp = base + 16 + 6 * q + 24 * p;
                red2(vp, v0, v1);
                red2(vp + 2, v2, v3);
                red2(vp + 4, v4, v5);
            }
            if (q == 0) atomicAdd(&g_cnt[src], 1.0f);
        }
    }
}

// ---------------- kernel 2: mean + residual + BN stats (+invariant restore) ----------------
__global__ __launch_bounds__(256) void k_stats(const float* __restrict__ node_attr) {
    __shared__ float sstat[48];
    int tid = threadIdx.x;
    if (tid < 48) sstat[tid] = 0.0f;
    __syncthreads();

    int n = blockIdx.x * 16 + (tid >> 4);  // grid covers exactly N_NODES
    int q = tid & 15;
    float cnt = g_cnt[n];
    float inv = 1.0f / fmaxf(cnt, 1.0f);
    float4 ag = *(const float4*)&g_agg[n * 64 + q * 4];
    // restore zero-invariant: each thread zeroes the exclusive 16B it consumed;
    // g_cnt word shared by 16 threads -> one writer after syncwarp
    *(float4*)&g_agg[n * 64 + q * 4] = make_float4(0, 0, 0, 0);
    __syncwarp();
    if (q == 0) g_cnt[n] = 0.0f;

    float4 na = *(const float4*)&node_attr[n * 64 + q * 4];
    float o[4] = {fmaf(ag.x, inv, na.x), fmaf(ag.y, inv, na.y),
                  fmaf(ag.z, inv, na.z), fmaf(ag.w, inv, na.w)};
    *(float4*)&g_out[n * 64 + q * 4] = make_float4(o[0], o[1], o[2], o[3]);
    if (q < 4) {
#pragma unroll
        for (int t = 0; t < 4; t++) {
            atomicAdd(&sstat[q * 4 + t], o[t]);
            atomicAdd(&sstat[16 + q * 4 + t], o[t] * o[t]);
        }
    } else {
#pragma unroll
        for (int t = 0; t < 4; t++) {
            int k = (q * 4 + t - 16) / 3;
            atomicAdd(&sstat[32 + k], o[t] * o[t]);
        }
    }
    __syncthreads();
    if (tid < 48) atomicAdd(&g_stats[tid], sstat[tid]);
}

// ---------------- kernel 3: normalize (BN finalize folded in) ----------------
__global__ __launch_bounds__(256) void k_norm(const float* __restrict__ bn_weight,
                                              const float* __restrict__ bn_bias,
                                              float* __restrict__ out) {
    __shared__ float prm[48];
    int tid = threadIdx.x;
    if (tid < 16) {
        float mean = g_stats[tid] * (1.0f / N_NODES);
        float var = g_stats[16 + tid] * (1.0f / N_NODES) - mean * mean;
        prm[tid] = mean;
        prm[16 + tid] = bn_weight[tid] * rsqrtf(var + BN_EPS);
        float fn = g_stats[32 + tid] * (1.0f / (3.0f * N_NODES));
        prm[32 + tid] = bn_weight[16 + tid] * rsqrtf(fn + BN_EPS);
    }
    __syncthreads();

    int idx = blockIdx.x * 256 + tid;  // grid covers exactly N_NODES*64
    int f = idx & 63;
    float o = g_out[idx];
    if (f < 16)
        out[idx] = (o - prm[f]) * prm[16 + f] + bn_bias[f];
    else
        out[idx] = o * prm[32 + (f - 16) / 3];
}

// ---------------- launch ----------------
extern "C" void kernel_launch(void* const* d_in, const int* in_sizes, int n_in,
                              void* d_out, int out_size) {
    const float* node_attr = (const float*)d_in[0];
    const float* edge_attr = (const float*)d_in[1];
    const float* edge_sh = (const float*)d_in[2];
    const float* w1 = (const float*)d_in[3];
    const float* b1 = (const float*)d_in[4];
    const float* w2 = (const float*)d_in[5];
    const float* b2 = (const float*)d_in[6];
    const float* bnw = (const float*)d_in[7];
    const float* bnb = (const float*)d_in[8];
    const int* eidx = (const int*)d_in[9];
    float* out = (float*)d_out;

    cudaFuncSetAttribute(k_tp, cudaFuncAttributeMaxDynamicSharedMemorySize, SMEM_TP);

    k_prep<<<128, 256>>>(w2, w1);
    k_tp<<<(N_EDGES + 127) / 128, 256, SMEM_TP>>>(node_attr, edge_sh, b2, eidx,
                                                  edge_attr, b1);
    k_stats<<<N_NODES / 16, 256>>>(node_attr);
    k_norm<<<(N_NODES * 64) / 256, 256>>>(bnw, bnb, out);
}

// round 17
// speedup vs baseline: 1.1728x; 1.0071x over previous
#include <cuda_runtime.h>
#include <cuda_bf16.h>

#define N_NODES 50000
#define N_EDGES 200000
#define MUL 16
#define ALPHA 0.17677669529663687f
#define INV_SQRT3 0.5773502691896258f
#define AIS (ALPHA * INV_SQRT3)
#define BN_EPS 1e-5f

typedef unsigned long long ull;
typedef unsigned int u32;

// ---------------- mma / ldmatrix / cp.async (baseline PTX, no 'a' gates) ----------------
__device__ __forceinline__ u32 smem_u32(const void* p) {
    u32 a;
    asm("{ .reg .u64 t; cvta.to.shared.u64 t, %1; cvt.u32.u64 %0, t; }" : "=r"(a) : "l"(p));
    return a;
}
__device__ __forceinline__ void ldsm4(u32& r0, u32& r1, u32& r2, u32& r3, u32 addr) {
    asm volatile("ldmatrix.sync.aligned.m8n8.x4.shared.b16 {%0,%1,%2,%3}, [%4];"
                 : "=r"(r0), "=r"(r1), "=r"(r2), "=r"(r3) : "r"(addr));
}
__device__ __forceinline__ void mma16816(float* d, const u32* a, u32 b0, u32 b1) {
    asm volatile(
        "mma.sync.aligned.m16n8k16.row.col.f32.bf16.bf16.f32 "
        "{%0,%1,%2,%3}, {%4,%5,%6,%7}, {%8,%9}, {%0,%1,%2,%3};"
        : "+f"(d[0]), "+f"(d[1]), "+f"(d[2]), "+f"(d[3])
        : "r"(a[0]), "r"(a[1]), "r"(a[2]), "r"(a[3]), "r"(b0), "r"(b1));
}
__device__ __forceinline__ void cpasync16(u32 dst, const void* src) {
    asm volatile("cp.async.ca.shared.global [%0], [%1], 16;" :: "r"(dst), "l"(src) : "memory");
}
#define CP_COMMIT() asm volatile("cp.async.commit_group;" ::: "memory")
#define CP_WAIT0() asm volatile("cp.async.wait_group 0;" ::: "memory")
#define CP_WAIT1() asm volatile("cp.async.wait_group 1;" ::: "memory")

// vectorized global f32 reduction (PTX 8.1+, sm_90+; 8B-aligned address required)
__device__ __forceinline__ void red2(float* p, float a, float b) {
    asm volatile("red.global.add.v2.f32 [%0], {%1, %2};" :: "l"(p), "f"(a), "f"(b) : "memory");
}

// pack two fp32 -> bf16x2 hi/lo split
__device__ __forceinline__ void split_pack(float va, float vb, u32& hi, u32& lo) {
    __nv_bfloat16 ha = __float2bfloat16(va), hb = __float2bfloat16(vb);
    float la = va - __bfloat162float(ha), lb = vb - __bfloat162float(hb);
    __nv_bfloat162 hp, lp;
    hp.x = ha; hp.y = hb;
    lp.x = __float2bfloat16(la); lp.y = __float2bfloat16(lb);
    hi = *(u32*)&hp;
    lo = *(u32*)&lp;
}

// ---------------- scratch ----------------
__device__ __align__(16) __nv_bfloat16 g_BThi[1024 * 64];
__device__ __align__(16) __nv_bfloat16 g_BTlo[1024 * 64];
__device__ __align__(16) __nv_bfloat16 g_W1Thi[64 * 64];
__device__ __align__(16) __nv_bfloat16 g_W1Tlo[64 * 64];
__device__ __align__(256) float g_agg[N_NODES * 64];  // zero on first run (BSS); restored by k_stats
__device__ float g_cnt[N_NODES];                      // same invariant
__device__ float g_out[N_NODES * 64];
__device__ float g_stats[48];

// ---------------- kernel 0: prep (zero g_stats + split w2^T and w1^T) ----------------
__global__ void k_prep(const float* __restrict__ w2, const float* __restrict__ w1) {
    int idx = blockIdx.x * blockDim.x + threadIdx.x;
    int stride = gridDim.x * blockDim.x;
    if (idx < 48) g_stats[idx] = 0.0f;

    // w2 split: g_BT[c][j] = split(w2[j][c])
    for (int i = idx; i < 65536; i += stride) {
        int j = i >> 10, c = i & 1023;
        float v = w2[i];
        __nv_bfloat16 hi = __float2bfloat16(v);
        g_BThi[c * 64 + j] = hi;
        g_BTlo[c * 64 + j] = __float2bfloat16(v - __bfloat162float(hi));
    }
    // w1 split: g_W1T[c][f] = split(w1[f][c])
    if (idx < 4096) {
        int f = idx >> 6, c = idx & 63;
        float v = w1[idx];
        __nv_bfloat16 hi = __float2bfloat16(v);
        g_W1Thi[c * 64 + f] = hi;
        g_W1Tlo[c * 64 + f] = __float2bfloat16(v - __bfloat162float(hi));
    }
}

// ---------------- kernel 1: fused GEMM1 + GEMM2 + TP + scatter ----------------
// 256 threads, 128 edges/block, 2 blocks/SM, warp owns 16 edges.
// B ring: 3 x 18432B (144B-padded rows). w1T staged in buf 2; B slices 0/1
// issued BEFORE GEMM1 so their GMEM latency hides behind the GEMM1 MMA burst.
#define OFF_AB 0            // 3 x 18432 ring
#define OFF_CA 55296
#define OFF_CB 63744
#define OFF_CX 72192
#define OFF_CD 80640
#define OFF_B2 105984
#define OFF_SHS 110080
#define SMEM_TP 112128

__global__ __launch_bounds__(256, 2) void k_tp(const float* __restrict__ node_attr,
                                               const float* __restrict__ edge_sh,
                                               const float* __restrict__ b2,
                                               const int* __restrict__ edge_index,
                                               const float* __restrict__ ea,
                                               const float* __restrict__ b1g) {
    extern __shared__ __align__(16) char smem[];
    float* cA = (float*)(smem + OFF_CA);
    float* cB = (float*)(smem + OFF_CB);
    float* cX = (float*)(smem + OFF_CX);
    float* cD = (float*)(smem + OFF_CD);
    float* b2s = (float*)(smem + OFF_B2);
    float* shs = (float*)(smem + OFF_SHS);
    __shared__ int srcs[128], dsts[128];

    int tid = threadIdx.x;
    int lane = tid & 31;
    int wid = tid >> 5;
    int e0 = blockIdx.x * 128;
    u32 sbase = smem_u32(smem);

    if (tid < 128) {
        int e = e0 + tid;
        bool val = e < N_EDGES;
        float4 sh = val ? ((const float4*)edge_sh)[e] : make_float4(0, 0, 0, 0);
        *(float4*)&shs[tid * 4] = sh;
        srcs[tid] = val ? edge_index[e] : 0;
        dsts[tid] = val ? edge_index[N_EDGES + e] : -1;
    }
    for (int idx = tid; idx < 1024; idx += 256) b2s[idx] = b2[idx];
    __syncthreads();

    // stage w1T hi/lo into ring buf 2 (rows padded to 144B), via cp.async
#pragma unroll 1
    for (int idx = tid; idx < 1024; idx += 256) {
        int half = idx >> 9, rem = idx & 511;
        int rr = rem >> 3, qq = rem & 7;
        const char* srcb = (const char*)(half ? g_W1Tlo : g_W1Thi);
        cpasync16(sbase + OFF_AB + 36864 + half * 9216 + rr * 144 + qq * 16,
                  srcb + rr * 128 + qq * 16);
    }
    CP_COMMIT();

    // coefficients [i][132e] (overlaps w1T copy)
    for (int idx = tid; idx < 2048; idx += 256) {
        int e = idx >> 4, i = idx & 15;
        int d = dsts[e];
        float ss = shs[e * 4], s1 = shs[e * 4 + 1], s2 = shs[e * 4 + 2], s3 = shs[e * 4 + 3];
        float xs = 0, x0 = 0, x1 = 0, x2 = 0;
        if (d >= 0) {
            xs = node_attr[d * 64 + i];
            const float* xp = &node_attr[d * 64 + 16 + 3 * i];
            x0 = xp[0]; x1 = xp[1]; x2 = xp[2];
        }
        cA[i * 132 + e] = ALPHA * ss * xs;
        cX[i * 132 + e] = AIS * xs;
        cB[i * 132 + e] = AIS * (x0 * s1 + x1 * s2 + x2 * s3);
        cD[(0 * 16 + i) * 132 + e] = AIS * ss * x0;
        cD[(1 * 16 + i) * 132 + e] = AIS * ss * x1;
        cD[(2 * 16 + i) * 132 + e] = AIS * ss * x2;
    }
    CP_WAIT0();
    __syncthreads();  // w1T staged (buf 2); coefficients visible

    // issue B slices 0 -> buf 0, 1 -> buf 1 NOW; latency hides behind GEMM1
#pragma unroll
    for (int ns = 0; ns < 2; ns++) {
        const char* bhp = (const char*)&g_BThi[ns * 64 * 64];
        const char* blp = (const char*)&g_BTlo[ns * 64 * 64];
        u32 dbase = sbase + OFF_AB + ns * 18432;
#pragma unroll 1
        for (int idx = tid; idx < 1024; idx += 256) {
            int half = idx >> 9, rem = idx & 511;
            int rr = rem >> 3, qq = rem & 7;
            cpasync16(dbase + half * 9216 + rr * 144 + qq * 16,
                      (half ? blp : bhp) + rr * 128 + qq * 16);
        }
        CP_COMMIT();
    }

    int q = lane & 3;
    int r = lane >> 2;
    int el0 = wid * 16 + r;
    u32 laneB = (u32)(((lane & 7) + ((lane >> 4) & 1) * 8) * 144 + ((lane >> 3) & 1) * 16);

    // ---- GEMM1: h = relu(ea @ w1 + b1), D-frags -> gemm2 A-frags (w1T in buf 2) ----
    u32 aH[4][4], aL[4][4];
    {
        float D1[4][8];
#pragma unroll
        for (int bq = 0; bq < 4; bq++)
#pragma unroll
            for (int z = 0; z < 8; z++) D1[bq][z] = 0.0f;

        bool v0 = (e0 + el0) < N_EDGES;
        bool v1 = (e0 + el0 + 8) < N_EDGES;
        const float* row0 = ea + (e0 + el0) * 64;
        const float* row1 = ea + (e0 + el0 + 8) * 64;
        float2 z2 = make_float2(0, 0);

#pragma unroll
        for (int ksin = 0; ksin < 4; ksin++) {
            int c = ksin * 16 + 2 * q;
            float2 x00 = v0 ? *(const float2*)&row0[c] : z2;
            float2 x10 = v1 ? *(const float2*)&row1[c] : z2;
            float2 x01 = v0 ? *(const float2*)&row0[c + 8] : z2;
            float2 x11 = v1 ? *(const float2*)&row1[c + 8] : z2;
            u32 eH[4], eL[4];
            split_pack(x00.x, x00.y, eH[0], eL[0]);
            split_pack(x10.x, x10.y, eH[1], eL[1]);
            split_pack(x01.x, x01.y, eH[2], eL[2]);
            split_pack(x11.x, x11.y, eH[3], eL[3]);

#pragma unroll
            for (int bq = 0; bq < 4; bq++) {
                u32 bh0, bh1, bh2, bh3, bl0, bl1, bl2, bl3;
                u32 ad = sbase + OFF_AB + 36864 + laneB + bq * 2304 + ksin * 32;
                ldsm4(bh0, bh1, bh2, bh3, ad);
                ldsm4(bl0, bl1, bl2, bl3, ad + 9216);
                mma16816(&D1[bq][0], eH, bh0, bh1);
                mma16816(&D1[bq][4], eH, bh2, bh3);
                mma16816(&D1[bq][0], eH, bl0, bl1);
                mma16816(&D1[bq][4], eH, bl2, bl3);
                mma16816(&D1[bq][0], eL, bh0, bh1);
                mma16816(&D1[bq][4], eL, bh2, bh3);
            }
        }

        // bias + relu + hi/lo split
#pragma unroll
        for (int ks = 0; ks < 4; ks++) {
            int cb = ks * 16 + 2 * q;
            float2 b01 = *(const float2*)&b1g[cb];
            float2 b89 = *(const float2*)&b1g[cb + 8];
            float d0 = fmaxf(D1[ks][0] + b01.x, 0.0f);
            float d1 = fmaxf(D1[ks][1] + b01.y, 0.0f);
            float d2 = fmaxf(D1[ks][2] + b01.x, 0.0f);
            float d3 = fmaxf(D1[ks][3] + b01.y, 0.0f);
            float d4 = fmaxf(D1[ks][4] + b89.x, 0.0f);
            float d5 = fmaxf(D1[ks][5] + b89.y, 0.0f);
            float d6 = fmaxf(D1[ks][6] + b89.x, 0.0f);
            float d7 = fmaxf(D1[ks][7] + b89.y, 0.0f);
            split_pack(d0, d1, aH[ks][0], aL[ks][0]);
            split_pack(d2, d3, aH[ks][1], aL[ks][1]);
            split_pack(d4, d5, aH[ks][2], aL[ks][2]);
            split_pack(d6, d7, aH[ks][3], aL[ks][3]);
        }
    }
    __syncthreads();  // all warps done reading w1T (buf 2) before slice 2 overwrites it

    float accS[2][4], accR[2][4], accV[2][4][3];
#pragma unroll
    for (int m = 0; m < 2; m++)
#pragma unroll
        for (int s = 0; s < 4; s++) {
            accS[m][s] = 0; accR[m][s] = 0;
            accV[m][s][0] = 0; accV[m][s][1] = 0; accV[m][s][2] = 0;
        }

#pragma unroll 1
    for (int sl = 0; sl < 16; sl++) {
        int t = sl >> 2, g = sl & 3;
        if (sl < 15) CP_WAIT1();   // slice sl landed; slice sl+1 may still fly
        else CP_WAIT0();
        __syncthreads();  // all warps done with slice sl-1 (its buffer gets rewritten now)
        if (sl < 14) {
            int ns = sl + 2;
            const char* bhp = (const char*)&g_BThi[ns * 64 * 64];
            const char* blp = (const char*)&g_BTlo[ns * 64 * 64];
            u32 dbase = sbase + OFF_AB + (ns % 3) * 18432;
#pragma unroll 1
            for (int idx = tid; idx < 1024; idx += 256) {
                int half = idx >> 9, rem = idx & 511;
                int rr = rem >> 3, qq = rem & 7;
                cpasync16(dbase + half * 9216 + rr * 144 + qq * 16,
                          (half ? blp : bhp) + rr * 128 + qq * 16);
            }
            CP_COMMIT();
        }

        u32 bHbase = sbase + OFF_AB + (sl % 3) * 18432 + laneB;
        u32 bLbase = bHbase + 9216;

        // bq pairs: 4 independent accumulation chains
#pragma unroll
        for (int bqp = 0; bqp < 2; bqp++) {
            float d[2][8];
#pragma unroll
            for (int u = 0; u < 2; u++)
#pragma unroll
                for (int z = 0; z < 8; z++) d[u][z] = 0.0f;

#pragma unroll
            for (int ks = 0; ks < 4; ks++) {
                u32 bh[2][4], bl[2][4];
#pragma unroll
                for (int u = 0; u < 2; u++) {
                    int bq = bqp * 2 + u;
                    ldsm4(bl[u][0], bl[u][1], bl[u][2], bl[u][3],
                          bLbase + bq * 2304 + ks * 32);
                    ldsm4(bh[u][0], bh[u][1], bh[u][2], bh[u][3],
                          bHbase + bq * 2304 + ks * 32);
                }
#pragma unroll
                for (int u = 0; u < 2; u++) {
                    mma16816(&d[u][0], aH[ks], bl[u][0], bl[u][1]);
                    mma16816(&d[u][4], aH[ks], bl[u][2], bl[u][3]);
                }
#pragma unroll
                for (int u = 0; u < 2; u++) {
                    mma16816(&d[u][0], aH[ks], bh[u][0], bh[u][1]);
                    mma16816(&d[u][4], aH[ks], bh[u][2], bh[u][3]);
                }
#pragma unroll
                for (int u = 0; u < 2; u++) {
                    mma16816(&d[u][0], aL[ks], bh[u][0], bh[u][1]);
                    mma16816(&d[u][4], aL[ks], bh[u][2], bh[u][3]);
                }
            }

            // epilogue for both bq of the pair
#pragma unroll
            for (int u = 0; u < 2; u++) {
                int bq = bqp * 2 + u;
                int i = g * 4 + bq;
                int colb = g * 64 + bq * 16 + 2 * q;
                if (t < 3) {
                    const float* cp = (t == 0) ? cA : (t == 1) ? cB : cX;
                    float cv0 = cp[i * 132 + el0];
                    float cv1 = cp[i * 132 + el0 + 8];
                    float (*acc)[4] = (t == 2) ? accR : accS;
#pragma unroll
                    for (int f = 0; f < 2; f++) {
                        float bb0 = b2s[t * 256 + colb + f * 8];
                        float bb1 = b2s[t * 256 + colb + f * 8 + 1];
                        acc[0][f * 2 + 0] += cv0 * (d[u][f * 4 + 0] + bb0);
                        acc[0][f * 2 + 1] += cv0 * (d[u][f * 4 + 1] + bb1);
                        acc[1][f * 2 + 0] += cv1 * (d[u][f * 4 + 2] + bb0);
                        acc[1][f * 2 + 1] += cv1 * (d[u][f * 4 + 3] + bb1);
                    }
                } else {
                    float cd0[3], cd1[3];
#pragma unroll
                    for (int mm = 0; mm < 3; mm++) {
                        cd0[mm] = cD[(mm * 16 + i) * 132 + el0];
                        cd1[mm] = cD[(mm * 16 + i) * 132 + el0 + 8];
                    }
#pragma unroll
                    for (int f = 0; f < 2; f++) {
                        float bb0 = b2s[768 + colb + f * 8];
                        float bb1 = b2s[768 + colb + f * 8 + 1];
                        float w00 = d[u][f * 4 + 0] + bb0, w01 = d[u][f * 4 + 1] + bb1;
                        float w10 = d[u][f * 4 + 2] + bb0, w11 = d[u][f * 4 + 3] + bb1;
#pragma unroll
                        for (int mm = 0; mm < 3; mm++) {
                            accV[0][f * 2 + 0][mm] += cd0[mm] * w00;
                            accV[0][f * 2 + 1][mm] += cd0[mm] * w01;
                            accV[1][f * 2 + 0][mm] += cd1[mm] * w10;
                            accV[1][f * 2 + 1][mm] += cd1[mm] * w11;
                        }
                    }
                }
            }
        }
    }

    // scatter: vectorized red.v2.f32
#pragma unroll
    for (int m = 0; m < 2; m++) {
        int el = el0 + 8 * m;
        if (e0 + el < N_EDGES) {
            int src = srcs[el];
            float s1 = shs[el * 4 + 1], s2 = shs[el * 4 + 2], s3 = shs[el * 4 + 3];
            float* base = &g_agg[src * 64];
            red2(base + 2 * q, accS[m][0], accS[m][1]);
            red2(base + 2 * q + 8, accS[m][2], accS[m][3]);
#pragma unroll
            for (int p = 0; p < 2; p++) {
                float r0 = accR[m][2 * p], r1 = accR[m][2 * p + 1];
                float v0 = accV[m][2 * p][0] + s1 * r0;
                float v1 = accV[m][2 * p][1] + s2 * r0;
                float v2 = accV[m][2 * p][2] + s3 * r0;
                float v3 = accV[m][2 * p + 1][0] + s1 * r1;
                float v4 = accV[m][2 * p + 1][1] + s2 * r1;
                float v5 = accV[m][2 * p + 1][2] + s3 * r1;
                float* vp = base + 16 + 6 * q + 24 * p;
                red2(vp, v0, v1);
                red2(vp + 2, v2, v3);
                red2(vp + 4, v4, v5);
            }
            if (q == 0) atomicAdd(&g_cnt[src], 1.0f);
        }
    }
}

// ---------------- kernel 2: mean + residual + BN stats (+invariant restore) ----------------
__global__ __launch_bounds__(256) void k_stats(const float* __restrict__ node_attr) {
    __shared__ float sstat[48];
    int tid = threadIdx.x;
    if (tid < 48) sstat[tid] = 0.0f;
    __syncthreads();

    int n = blockIdx.x * 16 + (tid >> 4);  // grid covers exactly N_NODES
    int q = tid & 15;
    float cnt = g_cnt[n];
    float inv = 1.0f / fmaxf(cnt, 1.0f);
    float4 ag = *(const float4*)&g_agg[n * 64 + q * 4];
    // restore zero-invariant: each thread zeroes the exclusive 16B it consumed
    *(float4*)&g_agg[n * 64 + q * 4] = make_float4(0, 0, 0, 0);
    __syncwarp();
    if (q == 0) g_cnt[n] = 0.0f;

    float4 na = *(const float4*)&node_attr[n * 64 + q * 4];
    float o[4] = {fmaf(ag.x, inv, na.x), fmaf(ag.y, inv, na.y),
                  fmaf(ag.z, inv, na.z), fmaf(ag.w, inv, na.w)};
    *(float4*)&g_out[n * 64 + q * 4] = make_float4(o[0], o[1], o[2], o[3]);
    if (q < 4) {
#pragma unroll
        for (int t = 0; t < 4; t++) {
            atomicAdd(&sstat[q * 4 + t], o[t]);
            atomicAdd(&sstat[16 + q * 4 + t], o[t] * o[t]);
        }
    } else {
#pragma unroll
        for (int t = 0; t < 4; t++) {
            int k = (q * 4 + t - 16) / 3;
            atomicAdd(&sstat[32 + k], o[t] * o[t]);
        }
    }
    __syncthreads();
    if (tid < 48) atomicAdd(&g_stats[tid], sstat[tid]);
}

// ---------------- kernel 3: normalize (BN finalize folded in; float4) ----------------
__global__ __launch_bounds__(256) void k_norm(const float* __restrict__ bn_weight,
                                              const float* __restrict__ bn_bias,
                                              float* __restrict__ out) {
    __shared__ float prm[64];
    int tid = threadIdx.x;
    if (tid < 16) {
        float mean = g_stats[tid] * (1.0f / N_NODES);
        float var = g_stats[16 + tid] * (1.0f / N_NODES) - mean * mean;
        prm[tid] = mean;
        prm[16 + tid] = bn_weight[tid] * rsqrtf(var + BN_EPS);
        float fn = g_stats[32 + tid] * (1.0f / (3.0f * N_NODES));
        prm[32 + tid] = bn_weight[16 + tid] * rsqrtf(fn + BN_EPS);
        prm[48 + tid] = bn_bias[tid];
    }
    __syncthreads();

    int idx4 = blockIdx.x * 256 + tid;   // float4 index; grid covers N_NODES*16
    int base = idx4 * 4;
    int f0 = base & 63;
    float4 o = *(const float4*)&g_out[base];
    float v[4] = {o.x, o.y, o.z, o.w};
#pragma unroll
    for (int c = 0; c < 4; c++) {
        int f = f0 + c;
        if (f < 16)
            v[c] = (v[c] - prm[f]) * prm[16 + f] + prm[48 + f];
        else
            v[c] = v[c] * prm[32 + (f - 16) / 3];
    }
    *(float4*)&out[base] = make_float4(v[0], v[1], v[2], v[3]);
}

// ---------------- launch ----------------
extern "C" void kernel_launch(void* const* d_in, const int* in_sizes, int n_in,
                              void* d_out, int out_size) {
    const float* node_attr = (const float*)d_in[0];
    const float* edge_attr = (const float*)d_in[1];
    const float* edge_sh = (const float*)d_in[2];
    const float* w1 = (const float*)d_in[3];
    const float* b1 = (const float*)d_in[4];
    const float* w2 = (const float*)d_in[5];
    const float* b2 = (const float*)d_in[6];
    const float* bnw = (const float*)d_in[7];
    const float* bnb = (const float*)d_in[8];
    const int* eidx = (const int*)d_in[9];
    float* out = (float*)d_out;

    cudaFuncSetAttribute(k_tp, cudaFuncAttributeMaxDynamicSharedMemorySize, SMEM_TP);

    k_prep<<<256, 256>>>(w2, w1);
    k_tp<<<(N_EDGES + 127) / 128, 256, SMEM_TP>>>(node_attr, edge_sh, b2, eidx,
                                                  edge_attr, b1);
    k_stats<<<N_NODES / 16, 256>>>(node_attr);
    k_norm<<<(N_NODES * 16) / 256, 256>>>(bnw, bnb, out);
}